// round 12
// baseline (speedup 1.0000x reference)
#include <cuda_runtime.h>
#include <math.h>
#include <mma.h>

using namespace nvcuda;

#define Hq   4
#define Lq   4096
#define Dq   1024
#define CHK  32
#define NCHK 128
#define MROWS 16384

// ---------------- scratch arena ----------------
constexpr size_t SZf      = 16777216ull;
constexpr size_t OFF_QPRE = 0;
constexpr size_t OFF_U    = 0;
constexpr size_t OFF_KPRE = SZf;
constexpr size_t OFF_W    = SZf;
constexpr size_t OFF_VPRE = 2*SZf;
constexpr size_t OFF_DELTA= 2*SZf;
constexpr size_t OFF_Q    = 3*SZf;
constexpr size_t OFF_K    = 4*SZf;
constexpr size_t OFF_V    = 5*SZf;
constexpr size_t OFF_EMAS = 6*SZf;
constexpr size_t OFF_EMAL = 7*SZf;
constexpr size_t OFF_OMIX = 8*SZf;
constexpr size_t OFF_Z    = 9*SZf;
constexpr size_t OFF_ATTN = OFF_Z + 8388608ull;
constexpr size_t OFF_BETA = OFF_ATTN + 2097152ull;
constexpr size_t OFF_GS   = OFF_BETA + 65536ull;
constexpr size_t OFF_GL   = OFF_GS + 65536ull;
constexpr size_t OFF_WGT  = OFF_GL + 65536ull;
constexpr size_t OFF_XR   = OFF_WGT + 262144ull;
constexpr size_t OFF_WQR  = OFF_XR + SZf;
constexpr size_t OFF_WKR  = OFF_WQR + 1048576ull;
constexpr size_t OFF_WVR  = OFF_WKR + 1048576ull;
constexpr size_t OFF_WTR  = OFF_WVR + 1048576ull;
constexpr size_t OFF_WOR  = OFF_WTR + 524288ull;
constexpr size_t ARENA_TOTAL = OFF_WOR + 1048576ull;

__device__ float g_arena[ARENA_TOTAL];

// chunk_pre smem
constexpr int QLD = 264;
constexpr int PRE_SMEM_FLOATS = 3*32*QLD + 3*32*36 + 32;
constexpr int PRE_SMEM_BYTES  = PRE_SMEM_FLOATS*4;        // 115328

// scan smem
constexpr int SLD = 36;
constexpr int SCAN_SMEM_FLOATS = 3*256*SLD + 3*32*SLD;
constexpr int SCAN_SMEM_BYTES  = SCAN_SMEM_FLOATS * 4;    // 124416

// GEMM tiling: 128x64, BK=32, 2-stage
constexpr int GBM = 128, GBN = 64, GBK = 32, GAP = 36;
constexpr int GSTAGE = (GBM+GBN)*GAP;
constexpr int GEMM_SMEM_BYTES = 2*GSTAGE*4;               // 55296

constexpr int GATE_SMEM_BYTES = 24*512*4;
constexpr int SP_SMEM_BYTES   = 12*1024*4;

__device__ __forceinline__ float sigm(float x){ return 1.f/(1.f+expf(-x)); }
__device__ __forceinline__ float silu(float x){ return x/(1.f+expf(-x)); }
__device__ __forceinline__ float tf32r(float x){ return wmma::__float_to_tf32(x); }

__device__ __forceinline__ float warp_sum(float v){
    #pragma unroll
    for (int o=16;o>0;o>>=1) v += __shfl_xor_sync(0xffffffffu, v, o);
    return v;
}

__device__ __forceinline__ void cp16(float* s, const float* g){
    unsigned a = (unsigned)__cvta_generic_to_shared(s);
    asm volatile("cp.async.cg.shared.global [%0], [%1], 16;" :: "r"(a), "l"(g));
}

// ---------------- tf32 rounding: x only ----------------
__global__ void round_x_kernel(const float* __restrict__ src, float* __restrict__ dst)
{
    int i = blockIdx.x*256 + threadIdx.x;   // 4194304 float4s
    float4 v = reinterpret_cast<const float4*>(src)[i];
    v.x = tf32r(v.x); v.y = tf32r(v.y); v.z = tf32r(v.z); v.w = tf32r(v.w);
    reinterpret_cast<float4*>(dst)[i] = v;
}

// ---------------- tf32 rounding: all weights ----------------
__global__ void round_w_kernel(const float* __restrict__ Wq, float* __restrict__ WqR,
                               const float* __restrict__ Wk, float* __restrict__ WkR,
                               const float* __restrict__ Wv, float* __restrict__ WvR,
                               const float* __restrict__ Wt, float* __restrict__ WtR,
                               const float* __restrict__ Wo, float* __restrict__ WoR)
{
    long i = (long)blockIdx.x*256 + threadIdx.x;
    const float* src; float* dst; long off;
    if (i < 262144)               { src=Wq; dst=WqR; off=i; }
    else if (i < 2*262144)        { src=Wk; dst=WkR; off=i-262144; }
    else if (i < 3*262144)        { src=Wv; dst=WvR; off=i-2*262144; }
    else if (i < 3*262144+131072) { src=Wt; dst=WtR; off=i-3*262144; }
    else if (i < 4*262144+131072) { src=Wo; dst=WoR; off=i-3*262144-131072; }
    else return;
    float4 v = reinterpret_cast<const float4*>(src)[off];
    v.x = tf32r(v.x); v.y = tf32r(v.y); v.z = tf32r(v.z); v.w = tf32r(v.w);
    reinterpret_cast<float4*>(dst)[off] = v;
}

// ---------------- GEMM core (inputs pre-rounded, NO cvt) ------------
__device__ __forceinline__ void gemm_body(const float* __restrict__ A, const float* __restrict__ W,
                                          const float* __restrict__ bias, float* __restrict__ C,
                                          int N, int K, int act, int m0, int n0, float* smem)
{
    const int tid = threadIdx.x, warp = tid>>5;
    const int tr = warp>>1, tcw = warp&1;
    const int lr = tid>>3, lc = (tid&7)*4;

    wmma::fragment<wmma::accumulator,16,16,8,float> acc[2][2];
    #pragma unroll
    for(int i=0;i<2;i++)
        #pragma unroll
        for(int j=0;j<2;j++) wmma::fill_fragment(acc[i][j], 0.f);

    const int KT = K/GBK;

    {
        float* As = smem;
        float* Ws = As + GBM*GAP;
        #pragma unroll
        for (int s=0;s<4;s++){
            int r = lr + s*32;
            cp16(&As[r*GAP+lc], &A[(size_t)(m0+r)*K + lc]);
        }
        #pragma unroll
        for (int s=0;s<2;s++){
            int r = lr + s*32;
            cp16(&Ws[r*GAP+lc], &W[(size_t)(n0+r)*K + lc]);
        }
        asm volatile("cp.async.commit_group;");
    }

    int buf = 0;
    for (int it=0; it<KT; ++it){
        if (it+1 < KT){
            float* As = smem + (buf^1)*GSTAGE;
            float* Ws = As + GBM*GAP;
            const int k0 = (it+1)*GBK;
            #pragma unroll
            for (int s=0;s<4;s++){
                int r = lr + s*32;
                cp16(&As[r*GAP+lc], &A[(size_t)(m0+r)*K + k0 + lc]);
            }
            #pragma unroll
            for (int s=0;s<2;s++){
                int r = lr + s*32;
                cp16(&Ws[r*GAP+lc], &W[(size_t)(n0+r)*K + k0 + lc]);
            }
            asm volatile("cp.async.commit_group;");
            asm volatile("cp.async.wait_group 1;");
        } else {
            asm volatile("cp.async.wait_group 0;");
        }
        __syncthreads();

        float* As = smem + buf*GSTAGE;
        float* Ws = As + GBM*GAP;
        #pragma unroll
        for (int kk=0; kk<GBK; kk+=8){
            wmma::fragment<wmma::matrix_a,16,16,8,wmma::precision::tf32,wmma::row_major> af[2];
            wmma::fragment<wmma::matrix_b,16,16,8,wmma::precision::tf32,wmma::col_major> bf[2];
            #pragma unroll
            for (int i=0;i<2;i++)
                wmma::load_matrix_sync(af[i], &As[(tr*32+i*16)*GAP + kk], GAP);
            #pragma unroll
            for (int j=0;j<2;j++)
                wmma::load_matrix_sync(bf[j], &Ws[(tcw*32+j*16)*GAP + kk], GAP);
            #pragma unroll
            for (int i=0;i<2;i++)
                #pragma unroll
                for (int j=0;j<2;j++)
                    wmma::mma_sync(acc[i][j], af[i], bf[j], acc[i][j]);
        }
        __syncthreads();
        buf ^= 1;
    }

    if (!bias && act == 0){
        #pragma unroll
        for (int i=0;i<2;i++)
            #pragma unroll
            for (int j=0;j<2;j++)
                wmma::store_matrix_sync(&C[(size_t)(m0+tr*32+i*16)*N + n0 + tcw*32 + j*16],
                                        acc[i][j], N, wmma::mem_row_major);
        return;
    }

    float* Cs = smem;
    #pragma unroll
    for (int i=0;i<2;i++)
        #pragma unroll
        for (int j=0;j<2;j++)
            wmma::store_matrix_sync(&Cs[(tr*32+i*16)*72 + tcw*32 + j*16], acc[i][j], 72, wmma::mem_row_major);
    __syncthreads();

    for (int idx = tid; idx < GBM*GBN/4; idx += 256){
        int row = idx >> 4, col = (idx & 15)*4;
        float4 v4 = *reinterpret_cast<float4*>(&Cs[row*72 + col]);
        float* vv = (float*)&v4;
        #pragma unroll
        for (int j=0;j<4;j++){
            float v = vv[j];
            if (bias) v += bias[n0+col+j];
            if (act==1) v = v/(1.f+expf(-v));
            vv[j] = v;
        }
        *reinterpret_cast<float4*>(&C[(size_t)(m0+row)*N + n0+col]) = v4;
    }
}

// ---------------- mega GEMM (4 blocks/SM forced) ----------
__global__ void __launch_bounds__(256, 4)
megagemm_kernel(const float* __restrict__ x,
                const float* __restrict__ Wq, const float* __restrict__ Wk,
                const float* __restrict__ Wv, const float* __restrict__ Wt,
                const float* __restrict__ bt,
                float* __restrict__ qpre, float* __restrict__ kpre,
                float* __restrict__ vpre, float* __restrict__ zb)
{
    extern __shared__ float smem[];
    const int bx = blockIdx.x;
    const int m0 = blockIdx.y*GBM;
    const float* W; float* C; const float* bias = nullptr;
    int N, act = 0, nb;
    if (bx < 16)      { W = Wq; C = qpre; N = 1024; nb = bx; }
    else if (bx < 32) { W = Wk; C = kpre; N = 1024; nb = bx-16; }
    else if (bx < 48) { W = Wv; C = vpre; N = 1024; nb = bx-32; }
    else              { W = Wt; C = zb;   N = 512;  nb = bx-48; bias = bt; act = 1; }
    gemm_body(x, W, bias, C, N, 1024, act, m0, nb*GBN, smem);
}

__global__ void __launch_bounds__(256, 4)
gemm_tf32_kernel(const float* __restrict__ A, const float* __restrict__ W,
                 float* __restrict__ C, int N, int K)
{
    extern __shared__ float smem[];
    gemm_body(A, W, nullptr, C, N, K, 0, blockIdx.y*GBM, blockIdx.x*GBN, smem);
}

// ---------------- causal depthwise conv + SiLU, float4, relayout ------
__global__ void conv_silu_kernel(const float* __restrict__ qp, const float* __restrict__ kp,
                                 const float* __restrict__ vp,
                                 const float* __restrict__ wq, const float* __restrict__ wk,
                                 const float* __restrict__ wv,
                                 float* __restrict__ qo, float* __restrict__ ko,
                                 float* __restrict__ vo)
{
    const int row = blockIdx.x;
    const int d4  = threadIdx.x * 4;
    const int l = row & (Lq-1), b = row >> 12;

    float4 wq_c[4], wk_c[4], wv_c[4];
    #pragma unroll
    for (int c=0;c<4;c++){
        wq_c[c] = *reinterpret_cast<const float4*>(wq + (d4+c)*4);
        wk_c[c] = *reinterpret_cast<const float4*>(wk + (d4+c)*4);
        wv_c[c] = *reinterpret_cast<const float4*>(wv + (d4+c)*4);
    }

    float aq[4] = {0,0,0,0}, ak[4] = {0,0,0,0}, av[4] = {0,0,0,0};
    #pragma unroll
    for (int j=0;j<4;j++){
        if (l - 3 + j >= 0){
            size_t idx = (size_t)(row - 3 + j)*Dq + d4;
            float4 xq = *reinterpret_cast<const float4*>(qp + idx);
            float4 xk = *reinterpret_cast<const float4*>(kp + idx);
            float4 xv = *reinterpret_cast<const float4*>(vp + idx);
            const float* xqf = (const float*)&xq;
            const float* xkf = (const float*)&xk;
            const float* xvf = (const float*)&xv;
            #pragma unroll
            for (int c=0;c<4;c++){
                aq[c] = fmaf(xqf[c], ((const float*)&wq_c[c])[j], aq[c]);
                ak[c] = fmaf(xkf[c], ((const float*)&wk_c[c])[j], ak[c]);
                av[c] = fmaf(xvf[c], ((const float*)&wv_c[c])[j], av[c]);
            }
        }
    }
    const int h = d4 >> 8, dk = d4 & 255;
    size_t o = ((size_t)(b*Hq + h)*Lq + l)*256 + dk;
    float4 oq, ok, ov;
    float* oqf = (float*)&oq; float* okf = (float*)&ok; float* ovf = (float*)&ov;
    #pragma unroll
    for (int c=0;c<4;c++){
        oqf[c] = silu(aq[c]);
        okf[c] = silu(ak[c]);
        ovf[c] = silu(av[c]);
    }
    *reinterpret_cast<float4*>(qo + o) = oq;
    *reinterpret_cast<float4*>(ko + o) = ok;
    *reinterpret_cast<float4*>(vo + o) = ov;
}

// ---------------- beta/gs/gl: 2 rows per warp, float4 x, weights in smem ------
__global__ void smallproj_kernel(const float* __restrict__ x,
                                 const float* __restrict__ Wb, const float* __restrict__ Wds,
                                 const float* __restrict__ bds, const float* __restrict__ Wdl,
                                 const float* __restrict__ bdl,
                                 float* __restrict__ beta, float* __restrict__ gs,
                                 float* __restrict__ gl)
{
    extern __shared__ float Ws[];
    const int tid = threadIdx.x, lane = tid&31, warp = tid>>5;
    for (int idx = tid; idx < 12*256; idx += 256){
        int r = idx >> 8, c4 = (idx & 255)*4;
        const float* src = (r<4) ? Wb + r*1024 + c4 :
                           (r<8) ? Wds + (r-4)*1024 + c4 : Wdl + (r-8)*1024 + c4;
        *reinterpret_cast<float4*>(&Ws[r*1024 + c4]) = *reinterpret_cast<const float4*>(src);
    }
    __syncthreads();

    #pragma unroll
    for (int rr=0; rr<2; rr++){
        const int row = blockIdx.x*16 + warp*2 + rr;
        const float* xr = x + (size_t)row*Dq;
        float acc[12];
        #pragma unroll
        for (int r=0;r<12;r++) acc[r]=0.f;
        #pragma unroll
        for (int it=0; it<8; it++){
            const int j = it*128 + lane*4;
            float4 xv4 = *reinterpret_cast<const float4*>(xr + j);
            const float* xv = (const float*)&xv4;
            #pragma unroll
            for (int r=0;r<12;r++){
                float a = acc[r];
                a = fmaf(xv[0], Ws[r*1024+j],   a);
                a = fmaf(xv[1], Ws[r*1024+j+1], a);
                a = fmaf(xv[2], Ws[r*1024+j+2], a);
                a = fmaf(xv[3], Ws[r*1024+j+3], a);
                acc[r] = a;
            }
        }
        #pragma unroll
        for (int r=0;r<12;r++) acc[r] = warp_sum(acc[r]);

        if (lane < 12){
            const int h = lane & 3;
            const int b = row >> 12, l = row & (Lq-1);
            size_t o = (size_t)(b*4 + h)*Lq + l;
            if (lane < 4)      beta[o] = sigm(acc[h]);
            else if (lane < 8) gs[o]   = sigm(acc[4+h] + bds[h]);
            else               gl[o]   = sigm(acc[8+h] + bdl[h]);
        }
    }
}

// ---------------- delta-rule per-chunk precompute (wmma) -------
__global__ void chunk_pre_kernel(float* __restrict__ q, float* __restrict__ k,
                                 const float* __restrict__ v, const float* __restrict__ beta,
                                 float* __restrict__ u, float* __restrict__ w,
                                 float* __restrict__ attn)
{
    extern __shared__ float sm[];
    float* qs  = sm;
    float* ks  = qs + 32*QLD;
    float* vs  = ks + 32*QLD;
    float* att = vs + 32*QLD;
    float* Lm  = att+ 32*36;
    float* Ti  = Lm + 32*36;
    float* bs  = Ti + 32*36;
    const int bh = blockIdx.x >> 7, c = blockIdx.x & 127;
    const int tid = threadIdx.x, lane = tid&31, wid = tid>>5;
    const size_t base = (size_t)bh*Lq + (size_t)c*CHK;

    for (int idx = tid; idx < 32*64; idx += 256){
        int i = idx >> 6, d4 = (idx & 63)*4;
        size_t g = (base+i)*256 + d4;
        *reinterpret_cast<float4*>(&qs[i*QLD+d4]) = *reinterpret_cast<const float4*>(&q[g]);
        *reinterpret_cast<float4*>(&ks[i*QLD+d4]) = *reinterpret_cast<const float4*>(&k[g]);
        *reinterpret_cast<float4*>(&vs[i*QLD+d4]) = *reinterpret_cast<const float4*>(&v[g]);
    }
    if (tid < 32) bs[tid] = beta[base + tid];
    __syncthreads();

    #pragma unroll
    for (int r=0;r<4;r++){
        int i = wid*4 + r;
        float sq=0.f, sk=0.f;
        for (int d=lane; d<256; d+=32){
            float a=qs[i*QLD+d]; sq=fmaf(a,a,sq);
            float bb=ks[i*QLD+d]; sk=fmaf(bb,bb,sk);
        }
        sq = warp_sum(sq); sk = warp_sum(sk);
        float rq = rsqrtf(sq + 1e-6f), rk = rsqrtf(sk + 1e-6f);
        for (int d=lane; d<256; d+=32){
            qs[i*QLD+d] = tf32r(qs[i*QLD+d]*rq);
            ks[i*QLD+d] = tf32r(ks[i*QLD+d]*rk);
        }
    }
    __syncthreads();

    for (int idx = tid; idx < 32*64; idx += 256){
        int i = idx>>6, d4 = (idx&63)*4;
        size_t g = (base+i)*256 + d4;
        *reinterpret_cast<float4*>(&q[g]) = *reinterpret_cast<float4*>(&qs[i*QLD+d4]);
        *reinterpret_cast<float4*>(&k[g]) = *reinterpret_cast<float4*>(&ks[i*QLD+d4]);
        float b = bs[i];
        float4 vv = *reinterpret_cast<float4*>(&vs[i*QLD+d4]);
        vv.x = tf32r(vv.x*b); vv.y = tf32r(vv.y*b); vv.z = tf32r(vv.z*b); vv.w = tf32r(vv.w*b);
        *reinterpret_cast<float4*>(&vs[i*QLD+d4]) = vv;
    }
    __syncthreads();

    {
        const int ww = wid & 3;
        const int j0 = (ww & 1)*16, i0 = (ww >> 1)*16;
        const float* Asrc = (wid < 4) ? qs : ks;
        float* dst = (wid < 4) ? att : Lm;
        wmma::fragment<wmma::accumulator,16,16,8,float> acc;
        wmma::fill_fragment(acc, 0.f);
        #pragma unroll 4
        for (int dk0 = 0; dk0 < 256; dk0 += 8){
            wmma::fragment<wmma::matrix_a,16,16,8,wmma::precision::tf32,wmma::row_major> af;
            wmma::load_matrix_sync(af, Asrc + i0*QLD + dk0, QLD);
            wmma::fragment<wmma::matrix_b,16,16,8,wmma::precision::tf32,wmma::col_major> bf;
            wmma::load_matrix_sync(bf, ks + j0*QLD + dk0, QLD);
            wmma::mma_sync(acc, af, bf, acc);
        }
        wmma::store_matrix_sync(dst + i0*36 + j0, acc, 36, wmma::mem_row_major);
    }
    __syncthreads();

    for (int idx = tid; idx < 1024; idx += 256){
        int i = idx>>5, j = idx&31;
        attn[(size_t)blockIdx.x*1024 + idx] = (j <= i) ? tf32r(att[i*36+j]) : 0.f;
        Lm[i*36+j] = (j < i) ? bs[i]*Lm[i*36+j] : 0.f;
    }
    __syncthreads();

    if (wid == 0){
        for (int i=0;i<32;i++){
            float xv = (lane==i) ? 1.f : 0.f;
            for (int p=0;p<i;p++) xv = fmaf(-Lm[i*36+p], Ti[p*36+lane], xv);
            Ti[i*36+lane] = xv;
            __syncwarp();
        }
    }
    __syncthreads();

    for (int idx = tid; idx < 1024; idx += 256){
        int i = idx>>5, j = idx&31;
        float t = Ti[i*36+j];
        Lm[i*36+j]  = tf32r(t);
        att[i*36+j] = -tf32r(t*bs[j]);
    }
    __syncthreads();

    #pragma unroll
    for (int t = 0; t < 8; t++){
        const int id = wid*8 + t;
        const bool isU = id < 32;
        const int tile = isU ? id : id - 32;
        const int i0 = (tile & 1)*16;
        const int j0 = (tile >> 1)*16;
        const float* A = isU ? Lm : att;
        const float* B = isU ? vs : ks;
        wmma::fragment<wmma::accumulator,16,16,8,float> acc;
        wmma::fill_fragment(acc, 0.f);
        #pragma unroll
        for (int m0 = 0; m0 < 32; m0 += 8){
            wmma::fragment<wmma::matrix_a,16,16,8,wmma::precision::tf32,wmma::row_major> af;
            wmma::load_matrix_sync(af, A + i0*36 + m0, 36);
            wmma::fragment<wmma::matrix_b,16,16,8,wmma::precision::tf32,wmma::row_major> bf;
            wmma::load_matrix_sync(bf, B + m0*QLD + j0, QLD);
            wmma::mma_sync(acc, af, bf, acc);
        }
        if (isU)
            wmma::store_matrix_sync(u + (base+i0)*256 + j0, acc, 256, wmma::mem_row_major);
        else
            wmma::store_matrix_sync(qs + i0*QLD + j0, acc, QLD, wmma::mem_row_major);
    }
    __syncthreads();

    for (int idx = tid; idx < 32*64; idx += 256){
        int i = idx>>6, d4 = (idx&63)*4;
        float4 vv = *reinterpret_cast<float4*>(&qs[i*QLD+d4]);
        vv.x = tf32r(vv.x); vv.y = tf32r(vv.y); vv.z = tf32r(vv.z); vv.w = tf32r(vv.w);
        *reinterpret_cast<float4*>(&w[(base+i)*256 + d4]) = vv;
    }
}

// ---------------- fused: delta-scan (0-127) + dual EMA (128-143) ----
__global__ void scan_ema_kernel(const float* __restrict__ q, const float* __restrict__ k,
                                const float* __restrict__ u, const float* __restrict__ w,
                                const float* __restrict__ attn, float* __restrict__ o,
                                const float* __restrict__ v, const float* __restrict__ gs,
                                const float* __restrict__ gl,
                                float* __restrict__ es, float* __restrict__ el)
{
    if (blockIdx.x >= 128){
        const int bh = blockIdx.x - 128;
        const int dv = threadIdx.x;
        const size_t vbase = (size_t)bh*Lq*256 + dv;
        const float* gsp = gs + (size_t)bh*Lq;
        const float* glp = gl + (size_t)bh*Lq;
        float ss = 0.f, sl = 0.f;
        #pragma unroll 8
        for (int t=0;t<Lq;t++){
            float vv = v[vbase + (size_t)t*256];
            float a = gsp[t], b2 = glp[t];
            ss = fmaf(a, ss, (1.f-a)*vv);
            sl = fmaf(b2, sl, (1.f-b2)*vv);
            es[vbase + (size_t)t*256] = ss;
            el[vbase + (size_t)t*256] = sl;
        }
        return;
    }

    extern __shared__ float sm[];
    float* S   = sm;
    float* Shi = S   + 256*SLD;
    float* Slo = Shi + 256*SLD;
    float* uh  = Slo + 256*SLD;
    float* uhh = uh  + 32*SLD;
    float* uhl = uhh + 32*SLD;
    const int bh = blockIdx.x >> 3;
    const int d0 = (blockIdx.x & 7) * 32;
    const int tid = threadIdx.x, warp = tid >> 5;

    for (int i = tid; i < 3*256*SLD; i += 256) sm[i] = 0.f;
    __syncthreads();

    wmma::fragment<wmma::accumulator,16,16,8,float> acc2;

    for (int c = 0; c < NCHK; ++c){
        const size_t base = (size_t)bh*Lq + (size_t)c*32;
        const float* qg = q + base*256;
        const float* kg = k + base*256;
        const float* wg = w + base*256;
        const float* ug = u + base*256 + d0;
        const float* ag = attn + ((size_t)bh*NCHK + c)*1024;
        float*       og = o + base*256 + d0;

        for (int idx = tid; idx < 256*32; idx += 256){
            int r = idx >> 5, cc = idx & 31;
            float s = S[r*SLD + cc];
            float hi = __uint_as_float(__float_as_uint(s) & 0xFFFFE000u);
            Shi[r*SLD + cc] = hi;
            Slo[r*SLD + cc] = tf32r(s - hi);
        }
        __syncthreads();

        if (warp < 4){
            const int i0 = (warp & 1)*16, j0 = (warp >> 1)*16;
            wmma::fragment<wmma::accumulator,16,16,8,float> acc;
            wmma::load_matrix_sync(acc, ug + (size_t)i0*256 + j0, 256, wmma::mem_row_major);
            #pragma unroll 4
            for (int dk0 = 0; dk0 < 256; dk0 += 8){
                wmma::fragment<wmma::matrix_a,16,16,8,wmma::precision::tf32,wmma::row_major> af;
                wmma::load_matrix_sync(af, wg + (size_t)i0*256 + dk0, 256);
                wmma::fragment<wmma::matrix_b,16,16,8,wmma::precision::tf32,wmma::row_major> bf;
                wmma::load_matrix_sync(bf, Shi + dk0*SLD + j0, SLD);
                wmma::mma_sync(acc, af, bf, acc);
                wmma::load_matrix_sync(bf, Slo + dk0*SLD + j0, SLD);
                wmma::mma_sync(acc, af, bf, acc);
            }
            wmma::store_matrix_sync(uh + i0*SLD + j0, acc, SLD, wmma::mem_row_major);
        } else {
            const int i0 = ((warp-4) & 1)*16, j0 = ((warp-4) >> 1)*16;
            wmma::fill_fragment(acc2, 0.f);
            #pragma unroll 4
            for (int dk0 = 0; dk0 < 256; dk0 += 8){
                wmma::fragment<wmma::matrix_a,16,16,8,wmma::precision::tf32,wmma::row_major> af;
                wmma::load_matrix_sync(af, qg + (size_t)i0*256 + dk0, 256);
                wmma::fragment<wmma::matrix_b,16,16,8,wmma::precision::tf32,wmma::row_major> bf;
                wmma::load_matrix_sync(bf, Shi + dk0*SLD + j0, SLD);
                wmma::mma_sync(acc2, af, bf, acc2);
            }
        }
        __syncthreads();

        for (int idx = tid; idx < 1024; idx += 256){
            int r = idx >> 5, cc = idx & 31;
            float s = uh[r*SLD + cc];
            float hi = __uint_as_float(__float_as_uint(s) & 0xFFFFE000u);
            uhh[r*SLD + cc] = hi;
            uhl[r*SLD + cc] = tf32r(s - hi);
        }
        __syncthreads();

        if (warp < 4){
            #pragma unroll
            for (int t = 0; t < 8; t++){
                const int id = warp*8 + t;
                const int dk0 = (id >> 1)*16, j0 = (id & 1)*16;
                wmma::fragment<wmma::accumulator,16,16,8,float> acc;
                wmma::load_matrix_sync(acc, S + dk0*SLD + j0, SLD, wmma::mem_row_major);
                #pragma unroll
                for (int i2 = 0; i2 < 32; i2 += 8){
                    wmma::fragment<wmma::matrix_a,16,16,8,wmma::precision::tf32,wmma::col_major> af;
                    wmma::load_matrix_sync(af, kg + (size_t)i2*256 + dk0, 256);
                    wmma::fragment<wmma::matrix_b,16,16,8,wmma::precision::tf32,wmma::row_major> bf;
                    wmma::load_matrix_sync(bf, uhh + i2*SLD + j0, SLD);
                    wmma::mma_sync(acc, af, bf, acc);
                    wmma::load_matrix_sync(bf, uhl + i2*SLD + j0, SLD);
                    wmma::mma_sync(acc, af, bf, acc);
                }
                wmma::store_matrix_sync(S + dk0*SLD + j0, acc, SLD, wmma::mem_row_major);
            }
        } else {
            const int i0 = ((warp-4) & 1)*16, j0 = ((warp-4) >> 1)*16;
            #pragma unroll
            for (int i2 = 0; i2 < 32; i2 += 8){
                wmma::fragment<wmma::matrix_a,16,16,8,wmma::precision::tf32,wmma::row_major> af;
                wmma::load_matrix_sync(af, ag + i0*32 + i2, 32);
                wmma::fragment<wmma::matrix_b,16,16,8,wmma::precision::tf32,wmma::row_major> bf;
                wmma::load_matrix_sync(bf, uhh + i2*SLD + j0, SLD);
                wmma::mma_sync(acc2, af, bf, acc2);
                wmma::load_matrix_sync(bf, uhl + i2*SLD + j0, SLD);
                wmma::mma_sync(acc2, af, bf, acc2);
            }
            wmma::store_matrix_sync(og + (size_t)i0*256 + j0, acc2, 256, wmma::mem_row_major);
        }
        __syncthreads();
    }
}

// ---------------- gate heads: 2 rows per warp, weights in smem --------------
__global__ void gate_head_kernel(const float* __restrict__ z,
                                 const float* __restrict__ Wc, const float* __restrict__ bc,
                                 const float* __restrict__ Wl, const float* __restrict__ bl,
                                 const float* __restrict__ Wg, const float* __restrict__ bg,
                                 const float* __restrict__ ltc, const float* __restrict__ ltf,
                                 float* __restrict__ wgt)
{
    extern __shared__ float Ws[];
    const int tid = threadIdx.x, lane = tid&31, warp = tid>>5;
    for (int idx = tid; idx < 24*128; idx += 256){
        int r = idx >> 7, c4 = (idx & 127)*4;
        const float* src = (r<8) ? Wc + r*512 + c4 :
                           (r<16)? Wl + (r-8)*512 + c4 : Wg + (r-16)*512 + c4;
        *reinterpret_cast<float4*>(&Ws[r*512 + c4]) = *reinterpret_cast<const float4*>(src);
    }
    __syncthreads();

    #pragma unroll
    for (int rr=0; rr<2; rr++){
        const int row = blockIdx.x*16 + warp*2 + rr;
        const float* zr = z + (size_t)row*512;
        float acc[24];
        #pragma unroll
        for (int r=0;r<24;r++) acc[r]=0.f;
        for (int j=lane; j<512; j+=32){
            float zv = zr[j];
            #pragma unroll
            for (int r=0;r<24;r++) acc[r] = fmaf(zv, Ws[r*512+j], acc[r]);
        }
        #pragma unroll
        for (int r=0;r<24;r++) acc[r] = warp_sum(acc[r]);

        if (lane < 4){
            const int h = lane;
            float tc = log1pf(expf(ltc[h])) + 1e-4f;
            float tf = log1pf(expf(ltf[h])) + 1e-4f;
            float c0 = acc[2*h]+bc[2*h],      c1 = acc[2*h+1]+bc[2*h+1];
            float l0 = acc[8+2*h]+bl[2*h],    l1 = acc[8+2*h+1]+bl[2*h+1];
            float g0 = acc[16+2*h]+bg[2*h],   g1 = acc[16+2*h+1]+bg[2*h+1];
            float pg0 = sigm((c0-c1)/tc), pg1 = 1.f - pg0;
            float q0  = sigm((l0-l1)/tf), q1 = 1.f - q0;
            float r0  = sigm((g0-g1)/tf), r1 = 1.f - r0;
            size_t o = (size_t)row*16 + h*4;
            wgt[o+0] = pg0*q0; wgt[o+1] = pg0*q1; wgt[o+2] = pg1*r0; wgt[o+3] = pg1*r1;
        }
    }
}

// ---------------- mix + per-head RMSNorm (rounds omix to tf32) --------------
__global__ void combine_kernel(const float* __restrict__ v, const float* __restrict__ es,
                               const float* __restrict__ el, const float* __restrict__ dl,
                               const float* __restrict__ wgt, const float* __restrict__ onw,
                               float* __restrict__ omix)
{
    const int gw = blockIdx.x*8 + (threadIdx.x>>5);
    const int row = gw >> 2, h = gw & 3;
    const int b = row >> 12, l = row & (Lq-1);
    const int lane = threadIdx.x & 31;
    const size_t gbase = ((size_t)(b*4+h)*Lq + l)*256;
    const float* wp = wgt + (size_t)row*16 + h*4;
    const float w0 = wp[0], w1 = wp[1], w2 = wp[2], w3 = wp[3];

    float4 vals[2];
    float ss = 0.f;
    #pragma unroll
    for (int s=0;s<2;s++){
        const int d = lane*4 + s*128;
        float4 a = *reinterpret_cast<const float4*>(v  + gbase + d);
        float4 b4= *reinterpret_cast<const float4*>(es + gbase + d);
        float4 c4= *reinterpret_cast<const float4*>(dl + gbase + d);
        float4 d4= *reinterpret_cast<const float4*>(el + gbase + d);
        float* av=(float*)&a; float* bv=(float*)&b4; float* cv=(float*)&c4; float* dv=(float*)&d4;
        float* ov=(float*)&vals[s];
        #pragma unroll
        for (int j=0;j<4;j++){
            float val = w0*av[j] + w1*bv[j] + w2*cv[j] + w3*dv[j];
            ov[j] = val;
            ss = fmaf(val, val, ss);
        }
    }
    ss = warp_sum(ss);
    const float rms = rsqrtf(ss*(1.f/256.f) + 1e-5f);
    float* op = omix + (size_t)row*1024 + h*256;
    #pragma unroll
    for (int s=0;s<2;s++){
        const int d = lane*4 + s*128;
        float4 w4 = *reinterpret_cast<const float4*>(onw + d);
        float* wv=(float*)&w4; float* ov=(float*)&vals[s];
        float4 r;
        float* rv=(float*)&r;
        #pragma unroll
        for (int j=0;j<4;j++) rv[j] = tf32r(ov[j]*rms*wv[j]);
        *reinterpret_cast<float4*>(op + d) = r;
    }
}

// ---------------- host ----------------
extern "C" void kernel_launch(void* const* d_in, const int* in_sizes, int n_in,
                              void* d_out, int out_size)
{
    const float* x      = (const float*)d_in[0];
    const float* Wq     = (const float*)d_in[1];
    const float* Wk     = (const float*)d_in[2];
    const float* Wv     = (const float*)d_in[3];
    const float* cqw    = (const float*)d_in[4];
    const float* ckw    = (const float*)d_in[5];
    const float* cvw    = (const float*)d_in[6];
    const float* Wb     = (const float*)d_in[7];
    const float* Wds    = (const float*)d_in[8];
    const float* bds    = (const float*)d_in[9];
    const float* Wdl    = (const float*)d_in[10];
    const float* bdl    = (const float*)d_in[11];
    const float* Wtrunk = (const float*)d_in[12];
    const float* btrunk = (const float*)d_in[13];
    const float* Wcoarse= (const float*)d_in[14];
    const float* bcoarse= (const float*)d_in[15];
    const float* Wlocal = (const float*)d_in[16];
    const float* blocal = (const float*)d_in[17];
    const float* Wglobal= (const float*)d_in[18];
    const float* bglobal= (const float*)d_in[19];
    const float* ltc    = (const float*)d_in[20];
    const float* ltf    = (const float*)d_in[21];
    const float* onw    = (const float*)d_in[22];
    const float* Wo     = (const float*)d_in[23];
    float* out = (float*)d_out;

    float* arena;
    cudaGetSymbolAddress((void**)&arena, g_arena);
    float* qpre = arena + OFF_QPRE;
    float* kpre = arena + OFF_KPRE;
    float* vpre = arena + OFF_VPRE;
    float* qb   = arena + OFF_Q;
    float* kb   = arena + OFF_K;
    float* vb   = arena + OFF_V;
    float* ub   = arena + OFF_U;
    float* wb   = arena + OFF_W;
    float* dlt  = arena + OFF_DELTA;
    float* emas = arena + OFF_EMAS;
    float* emal = arena + OFF_EMAL;
    float* omix = arena + OFF_OMIX;
    float* zb   = arena + OFF_Z;
    float* attn = arena + OFF_ATTN;
    float* beta = arena + OFF_BETA;
    float* gs   = arena + OFF_GS;
    float* gl   = arena + OFF_GL;
    float* wgt  = arena + OFF_WGT;
    float* xr   = arena + OFF_XR;
    float* WqR  = arena + OFF_WQR;
    float* WkR  = arena + OFF_WKR;
    float* WvR  = arena + OFF_WVR;
    float* WtR  = arena + OFF_WTR;
    float* WoR  = arena + OFF_WOR;

    cudaFuncSetAttribute(megagemm_kernel,  cudaFuncAttributeMaxDynamicSharedMemorySize, GEMM_SMEM_BYTES);
    cudaFuncSetAttribute(gemm_tf32_kernel, cudaFuncAttributeMaxDynamicSharedMemorySize, GEMM_SMEM_BYTES);
    cudaFuncSetAttribute(chunk_pre_kernel, cudaFuncAttributeMaxDynamicSharedMemorySize, PRE_SMEM_BYTES);
    cudaFuncSetAttribute(scan_ema_kernel,  cudaFuncAttributeMaxDynamicSharedMemorySize, SCAN_SMEM_BYTES);
    cudaFuncSetAttribute(gate_head_kernel, cudaFuncAttributeMaxDynamicSharedMemorySize, GATE_SMEM_BYTES);
    cudaFuncSetAttribute(smallproj_kernel, cudaFuncAttributeMaxDynamicSharedMemorySize, SP_SMEM_BYTES);

    dim3 blk(256);

    // 0: round x
    round_x_kernel<<<16384, blk>>>(x, xr);

    // 1: round weights
    round_w_kernel<<<4608, blk>>>(Wq, WqR, Wk, WkR, Wv, WvR, Wtrunk, WtR, Wo, WoR);

    // 2: beta / decays
    smallproj_kernel<<<MROWS/16, blk, SP_SMEM_BYTES>>>(x, Wb, Wds, bds, Wdl, bdl, beta, gs, gl);

    // 3: fused Q/K/V/trunk projections  (profiled slot)
    megagemm_kernel<<<dim3(56, MROWS/GBM), blk, GEMM_SMEM_BYTES>>>(
        xr, WqR, WkR, WvR, WtR, btrunk, qpre, kpre, vpre, zb);

    // 4: conv + silu + relayout
    conv_silu_kernel<<<MROWS, blk>>>(qpre, kpre, vpre, cqw, ckw, cvw, qb, kb, vb);

    // 5: delta rule precompute
    chunk_pre_kernel<<<2048, blk, PRE_SMEM_BYTES>>>(qb, kb, vb, beta, ub, wb, attn);

    // 6: fused scan + EMA
    scan_ema_kernel<<<144, blk, SCAN_SMEM_BYTES>>>(qb, kb, ub, wb, attn, dlt,
                                                   vb, gs, gl, emas, emal);

    // 7: gate heads
    gate_head_kernel<<<MROWS/16, blk, GATE_SMEM_BYTES>>>(zb, Wcoarse, bcoarse, Wlocal, blocal,
                                                         Wglobal, bglobal, ltc, ltf, wgt);

    // 8: combine + RMSNorm
    combine_kernel<<<MROWS/2, blk>>>(vb, emas, emal, dlt, wgt, onw, omix);

    // 9: output projection
    gemm_tf32_kernel<<<dim3(1024/GBN, MROWS/GBM), blk, GEMM_SMEM_BYTES>>>(omix, WoR, out, 1024, 1024);
}

// round 13
// speedup vs baseline: 1.0204x; 1.0204x over previous
#include <cuda_runtime.h>
#include <math.h>
#include <mma.h>

using namespace nvcuda;

#define Hq   4
#define Lq   4096
#define Dq   1024
#define CHK  32
#define NCHK 128
#define MROWS 16384

// ---------------- scratch arena ----------------
constexpr size_t SZf      = 16777216ull;
constexpr size_t OFF_QPRE = 0;
constexpr size_t OFF_U    = 0;
constexpr size_t OFF_KPRE = SZf;
constexpr size_t OFF_W    = SZf;
constexpr size_t OFF_VPRE = 2*SZf;
constexpr size_t OFF_DELTA= 2*SZf;
constexpr size_t OFF_Q    = 3*SZf;
constexpr size_t OFF_K    = 4*SZf;
constexpr size_t OFF_V    = 5*SZf;
constexpr size_t OFF_EMAS = 6*SZf;
constexpr size_t OFF_EMAL = 7*SZf;
constexpr size_t OFF_OMIX = 8*SZf;
constexpr size_t OFF_Z    = 9*SZf;
constexpr size_t OFF_ATTN = OFF_Z + 8388608ull;
constexpr size_t OFF_BETA = OFF_ATTN + 2097152ull;
constexpr size_t OFF_GS   = OFF_BETA + 65536ull;
constexpr size_t OFF_GL   = OFF_GS + 65536ull;
constexpr size_t OFF_WGT  = OFF_GL + 65536ull;
constexpr size_t OFF_XR   = OFF_WGT + 262144ull;
constexpr size_t OFF_WQR  = OFF_XR + SZf;
constexpr size_t OFF_WKR  = OFF_WQR + 1048576ull;
constexpr size_t OFF_WVR  = OFF_WKR + 1048576ull;
constexpr size_t OFF_WTR  = OFF_WVR + 1048576ull;
constexpr size_t OFF_WOR  = OFF_WTR + 524288ull;
constexpr size_t ARENA_TOTAL = OFF_WOR + 1048576ull;

__device__ float g_arena[ARENA_TOTAL];

// chunk_pre smem
constexpr int QLD = 264;
constexpr int PRE_SMEM_FLOATS = 3*32*QLD + 3*32*36 + 32;
constexpr int PRE_SMEM_BYTES  = PRE_SMEM_FLOATS*4;        // 115328

// scan smem: S, Shi, Slo (256x36) + uhh, uhl (32x36)
constexpr int SLD = 36;
constexpr int SCAN_SMEM_FLOATS = 3*256*SLD + 2*32*SLD;
constexpr int SCAN_SMEM_BYTES  = SCAN_SMEM_FLOATS * 4;    // 119808

// GEMM tiling: 128x64, BK=32, 2-stage
constexpr int GBM = 128, GBN = 64, GBK = 32, GAP = 36;
constexpr int GSTAGE = (GBM+GBN)*GAP;
constexpr int GEMM_SMEM_BYTES = 2*GSTAGE*4;               // 55296

constexpr int GATE_SMEM_BYTES = 24*512*4;
constexpr int SP_SMEM_BYTES   = 12*1024*4;

__device__ __forceinline__ float sigm(float x){ return 1.f/(1.f+expf(-x)); }
__device__ __forceinline__ float silu(float x){ return x/(1.f+expf(-x)); }
__device__ __forceinline__ float tf32r(float x){ return wmma::__float_to_tf32(x); }

__device__ __forceinline__ float warp_sum(float v){
    #pragma unroll
    for (int o=16;o>0;o>>=1) v += __shfl_xor_sync(0xffffffffu, v, o);
    return v;
}

__device__ __forceinline__ void cp16(float* s, const float* g){
    unsigned a = (unsigned)__cvta_generic_to_shared(s);
    asm volatile("cp.async.cg.shared.global [%0], [%1], 16;" :: "r"(a), "l"(g));
}

// ---------------- tf32 rounding: x only ----------------
__global__ void round_x_kernel(const float* __restrict__ src, float* __restrict__ dst)
{
    int i = blockIdx.x*256 + threadIdx.x;
    float4 v = reinterpret_cast<const float4*>(src)[i];
    v.x = tf32r(v.x); v.y = tf32r(v.y); v.z = tf32r(v.z); v.w = tf32r(v.w);
    reinterpret_cast<float4*>(dst)[i] = v;
}

// ---------------- tf32 rounding: all weights ----------------
__global__ void round_w_kernel(const float* __restrict__ Wq, float* __restrict__ WqR,
                               const float* __restrict__ Wk, float* __restrict__ WkR,
                               const float* __restrict__ Wv, float* __restrict__ WvR,
                               const float* __restrict__ Wt, float* __restrict__ WtR,
                               const float* __restrict__ Wo, float* __restrict__ WoR)
{
    long i = (long)blockIdx.x*256 + threadIdx.x;
    const float* src; float* dst; long off;
    if (i < 262144)               { src=Wq; dst=WqR; off=i; }
    else if (i < 2*262144)        { src=Wk; dst=WkR; off=i-262144; }
    else if (i < 3*262144)        { src=Wv; dst=WvR; off=i-2*262144; }
    else if (i < 3*262144+131072) { src=Wt; dst=WtR; off=i-3*262144; }
    else if (i < 4*262144+131072) { src=Wo; dst=WoR; off=i-3*262144-131072; }
    else return;
    float4 v = reinterpret_cast<const float4*>(src)[off];
    v.x = tf32r(v.x); v.y = tf32r(v.y); v.z = tf32r(v.z); v.w = tf32r(v.w);
    reinterpret_cast<float4*>(dst)[off] = v;
}

// ---------------- GEMM core (inputs pre-rounded, NO cvt) ------------
__device__ __forceinline__ void gemm_body(const float* __restrict__ A, const float* __restrict__ W,
                                          const float* __restrict__ bias, float* __restrict__ C,
                                          int N, int K, int act, int m0, int n0, float* smem)
{
    const int tid = threadIdx.x, warp = tid>>5;
    const int tr = warp>>1, tcw = warp&1;
    const int lr = tid>>3, lc = (tid&7)*4;

    wmma::fragment<wmma::accumulator,16,16,8,float> acc[2][2];
    #pragma unroll
    for(int i=0;i<2;i++)
        #pragma unroll
        for(int j=0;j<2;j++) wmma::fill_fragment(acc[i][j], 0.f);

    const int KT = K/GBK;

    {
        float* As = smem;
        float* Ws = As + GBM*GAP;
        #pragma unroll
        for (int s=0;s<4;s++){
            int r = lr + s*32;
            cp16(&As[r*GAP+lc], &A[(size_t)(m0+r)*K + lc]);
        }
        #pragma unroll
        for (int s=0;s<2;s++){
            int r = lr + s*32;
            cp16(&Ws[r*GAP+lc], &W[(size_t)(n0+r)*K + lc]);
        }
        asm volatile("cp.async.commit_group;");
    }

    int buf = 0;
    for (int it=0; it<KT; ++it){
        if (it+1 < KT){
            float* As = smem + (buf^1)*GSTAGE;
            float* Ws = As + GBM*GAP;
            const int k0 = (it+1)*GBK;
            #pragma unroll
            for (int s=0;s<4;s++){
                int r = lr + s*32;
                cp16(&As[r*GAP+lc], &A[(size_t)(m0+r)*K + k0 + lc]);
            }
            #pragma unroll
            for (int s=0;s<2;s++){
                int r = lr + s*32;
                cp16(&Ws[r*GAP+lc], &W[(size_t)(n0+r)*K + k0 + lc]);
            }
            asm volatile("cp.async.commit_group;");
            asm volatile("cp.async.wait_group 1;");
        } else {
            asm volatile("cp.async.wait_group 0;");
        }
        __syncthreads();

        float* As = smem + buf*GSTAGE;
        float* Ws = As + GBM*GAP;
        #pragma unroll
        for (int kk=0; kk<GBK; kk+=8){
            wmma::fragment<wmma::matrix_a,16,16,8,wmma::precision::tf32,wmma::row_major> af[2];
            wmma::fragment<wmma::matrix_b,16,16,8,wmma::precision::tf32,wmma::col_major> bf[2];
            #pragma unroll
            for (int i=0;i<2;i++)
                wmma::load_matrix_sync(af[i], &As[(tr*32+i*16)*GAP + kk], GAP);
            #pragma unroll
            for (int j=0;j<2;j++)
                wmma::load_matrix_sync(bf[j], &Ws[(tcw*32+j*16)*GAP + kk], GAP);
            #pragma unroll
            for (int i=0;i<2;i++)
                #pragma unroll
                for (int j=0;j<2;j++)
                    wmma::mma_sync(acc[i][j], af[i], bf[j], acc[i][j]);
        }
        __syncthreads();
        buf ^= 1;
    }

    if (!bias && act == 0){
        #pragma unroll
        for (int i=0;i<2;i++)
            #pragma unroll
            for (int j=0;j<2;j++)
                wmma::store_matrix_sync(&C[(size_t)(m0+tr*32+i*16)*N + n0 + tcw*32 + j*16],
                                        acc[i][j], N, wmma::mem_row_major);
        return;
    }

    float* Cs = smem;
    #pragma unroll
    for (int i=0;i<2;i++)
        #pragma unroll
        for (int j=0;j<2;j++)
            wmma::store_matrix_sync(&Cs[(tr*32+i*16)*72 + tcw*32 + j*16], acc[i][j], 72, wmma::mem_row_major);
    __syncthreads();

    for (int idx = tid; idx < GBM*GBN/4; idx += 256){
        int row = idx >> 4, col = (idx & 15)*4;
        float4 v4 = *reinterpret_cast<float4*>(&Cs[row*72 + col]);
        float* vv = (float*)&v4;
        #pragma unroll
        for (int j=0;j<4;j++){
            float v = vv[j];
            if (bias) v += bias[n0+col+j];
            if (act==1) v = v/(1.f+expf(-v));
            vv[j] = v;
        }
        *reinterpret_cast<float4*>(&C[(size_t)(m0+row)*N + n0+col]) = v4;
    }
}

// ---------------- mega GEMM ----------
__global__ void __launch_bounds__(256, 4)
megagemm_kernel(const float* __restrict__ x,
                const float* __restrict__ Wq, const float* __restrict__ Wk,
                const float* __restrict__ Wv, const float* __restrict__ Wt,
                const float* __restrict__ bt,
                float* __restrict__ qpre, float* __restrict__ kpre,
                float* __restrict__ vpre, float* __restrict__ zb)
{
    extern __shared__ float smem[];
    const int bx = blockIdx.x;
    const int m0 = blockIdx.y*GBM;
    const float* W; float* C; const float* bias = nullptr;
    int N, act = 0, nb;
    if (bx < 16)      { W = Wq; C = qpre; N = 1024; nb = bx; }
    else if (bx < 32) { W = Wk; C = kpre; N = 1024; nb = bx-16; }
    else if (bx < 48) { W = Wv; C = vpre; N = 1024; nb = bx-32; }
    else              { W = Wt; C = zb;   N = 512;  nb = bx-48; bias = bt; act = 1; }
    gemm_body(x, W, bias, C, N, 1024, act, m0, nb*GBN, smem);
}

__global__ void __launch_bounds__(256, 4)
gemm_tf32_kernel(const float* __restrict__ A, const float* __restrict__ W,
                 float* __restrict__ C, int N, int K)
{
    extern __shared__ float smem[];
    gemm_body(A, W, nullptr, C, N, K, 0, blockIdx.y*GBM, blockIdx.x*GBN, smem);
}

// ---------------- causal depthwise conv + SiLU, float4, relayout ------
__global__ void conv_silu_kernel(const float* __restrict__ qp, const float* __restrict__ kp,
                                 const float* __restrict__ vp,
                                 const float* __restrict__ wq, const float* __restrict__ wk,
                                 const float* __restrict__ wv,
                                 float* __restrict__ qo, float* __restrict__ ko,
                                 float* __restrict__ vo)
{
    const int row = blockIdx.x;
    const int d4  = threadIdx.x * 4;
    const int l = row & (Lq-1), b = row >> 12;

    float4 wq_c[4], wk_c[4], wv_c[4];
    #pragma unroll
    for (int c=0;c<4;c++){
        wq_c[c] = *reinterpret_cast<const float4*>(wq + (d4+c)*4);
        wk_c[c] = *reinterpret_cast<const float4*>(wk + (d4+c)*4);
        wv_c[c] = *reinterpret_cast<const float4*>(wv + (d4+c)*4);
    }

    float aq[4] = {0,0,0,0}, ak[4] = {0,0,0,0}, av[4] = {0,0,0,0};
    #pragma unroll
    for (int j=0;j<4;j++){
        if (l - 3 + j >= 0){
            size_t idx = (size_t)(row - 3 + j)*Dq + d4;
            float4 xq = *reinterpret_cast<const float4*>(qp + idx);
            float4 xk = *reinterpret_cast<const float4*>(kp + idx);
            float4 xv = *reinterpret_cast<const float4*>(vp + idx);
            const float* xqf = (const float*)&xq;
            const float* xkf = (const float*)&xk;
            const float* xvf = (const float*)&xv;
            #pragma unroll
            for (int c=0;c<4;c++){
                aq[c] = fmaf(xqf[c], ((const float*)&wq_c[c])[j], aq[c]);
                ak[c] = fmaf(xkf[c], ((const float*)&wk_c[c])[j], ak[c]);
                av[c] = fmaf(xvf[c], ((const float*)&wv_c[c])[j], av[c]);
            }
        }
    }
    const int h = d4 >> 8, dk = d4 & 255;
    size_t o = ((size_t)(b*Hq + h)*Lq + l)*256 + dk;
    float4 oq, ok, ov;
    float* oqf = (float*)&oq; float* okf = (float*)&ok; float* ovf = (float*)&ov;
    #pragma unroll
    for (int c=0;c<4;c++){
        oqf[c] = silu(aq[c]);
        okf[c] = silu(ak[c]);
        ovf[c] = silu(av[c]);
    }
    *reinterpret_cast<float4*>(qo + o) = oq;
    *reinterpret_cast<float4*>(ko + o) = ok;
    *reinterpret_cast<float4*>(vo + o) = ov;
}

// ---------------- beta/gs/gl: 2 rows per warp, float4 x, weights in smem ------
__global__ void smallproj_kernel(const float* __restrict__ x,
                                 const float* __restrict__ Wb, const float* __restrict__ Wds,
                                 const float* __restrict__ bds, const float* __restrict__ Wdl,
                                 const float* __restrict__ bdl,
                                 float* __restrict__ beta, float* __restrict__ gs,
                                 float* __restrict__ gl)
{
    extern __shared__ float Ws[];
    const int tid = threadIdx.x, lane = tid&31, warp = tid>>5;
    for (int idx = tid; idx < 12*256; idx += 256){
        int r = idx >> 8, c4 = (idx & 255)*4;
        const float* src = (r<4) ? Wb + r*1024 + c4 :
                           (r<8) ? Wds + (r-4)*1024 + c4 : Wdl + (r-8)*1024 + c4;
        *reinterpret_cast<float4*>(&Ws[r*1024 + c4]) = *reinterpret_cast<const float4*>(src);
    }
    __syncthreads();

    #pragma unroll
    for (int rr=0; rr<2; rr++){
        const int row = blockIdx.x*16 + warp*2 + rr;
        const float* xr = x + (size_t)row*Dq;
        float acc[12];
        #pragma unroll
        for (int r=0;r<12;r++) acc[r]=0.f;
        #pragma unroll
        for (int it=0; it<8; it++){
            const int j = it*128 + lane*4;
            float4 xv4 = *reinterpret_cast<const float4*>(xr + j);
            const float* xv = (const float*)&xv4;
            #pragma unroll
            for (int r=0;r<12;r++){
                float a = acc[r];
                a = fmaf(xv[0], Ws[r*1024+j],   a);
                a = fmaf(xv[1], Ws[r*1024+j+1], a);
                a = fmaf(xv[2], Ws[r*1024+j+2], a);
                a = fmaf(xv[3], Ws[r*1024+j+3], a);
                acc[r] = a;
            }
        }
        #pragma unroll
        for (int r=0;r<12;r++) acc[r] = warp_sum(acc[r]);

        if (lane < 12){
            const int h = lane & 3;
            const int b = row >> 12, l = row & (Lq-1);
            size_t o = (size_t)(b*4 + h)*Lq + l;
            if (lane < 4)      beta[o] = sigm(acc[h]);
            else if (lane < 8) gs[o]   = sigm(acc[4+h] + bds[h]);
            else               gl[o]   = sigm(acc[8+h] + bdl[h]);
        }
    }
}

// ---------------- delta-rule per-chunk precompute (wmma) -------
__global__ void chunk_pre_kernel(float* __restrict__ q, float* __restrict__ k,
                                 const float* __restrict__ v, const float* __restrict__ beta,
                                 float* __restrict__ u, float* __restrict__ w,
                                 float* __restrict__ attn)
{
    extern __shared__ float sm[];
    float* qs  = sm;
    float* ks  = qs + 32*QLD;
    float* vs  = ks + 32*QLD;
    float* att = vs + 32*QLD;
    float* Lm  = att+ 32*36;
    float* Ti  = Lm + 32*36;
    float* bs  = Ti + 32*36;
    const int bh = blockIdx.x >> 7, c = blockIdx.x & 127;
    const int tid = threadIdx.x, lane = tid&31, wid = tid>>5;
    const size_t base = (size_t)bh*Lq + (size_t)c*CHK;

    for (int idx = tid; idx < 32*64; idx += 256){
        int i = idx >> 6, d4 = (idx & 63)*4;
        size_t g = (base+i)*256 + d4;
        *reinterpret_cast<float4*>(&qs[i*QLD+d4]) = *reinterpret_cast<const float4*>(&q[g]);
        *reinterpret_cast<float4*>(&ks[i*QLD+d4]) = *reinterpret_cast<const float4*>(&k[g]);
        *reinterpret_cast<float4*>(&vs[i*QLD+d4]) = *reinterpret_cast<const float4*>(&v[g]);
    }
    if (tid < 32) bs[tid] = beta[base + tid];
    __syncthreads();

    #pragma unroll
    for (int r=0;r<4;r++){
        int i = wid*4 + r;
        float sq=0.f, sk=0.f;
        for (int d=lane; d<256; d+=32){
            float a=qs[i*QLD+d]; sq=fmaf(a,a,sq);
            float bb=ks[i*QLD+d]; sk=fmaf(bb,bb,sk);
        }
        sq = warp_sum(sq); sk = warp_sum(sk);
        float rq = rsqrtf(sq + 1e-6f), rk = rsqrtf(sk + 1e-6f);
        for (int d=lane; d<256; d+=32){
            qs[i*QLD+d] = tf32r(qs[i*QLD+d]*rq);
            ks[i*QLD+d] = tf32r(ks[i*QLD+d]*rk);
        }
    }
    __syncthreads();

    for (int idx = tid; idx < 32*64; idx += 256){
        int i = idx>>6, d4 = (idx&63)*4;
        size_t g = (base+i)*256 + d4;
        *reinterpret_cast<float4*>(&q[g]) = *reinterpret_cast<float4*>(&qs[i*QLD+d4]);
        *reinterpret_cast<float4*>(&k[g]) = *reinterpret_cast<float4*>(&ks[i*QLD+d4]);
        float b = bs[i];
        float4 vv = *reinterpret_cast<float4*>(&vs[i*QLD+d4]);
        vv.x = tf32r(vv.x*b); vv.y = tf32r(vv.y*b); vv.z = tf32r(vv.z*b); vv.w = tf32r(vv.w*b);
        *reinterpret_cast<float4*>(&vs[i*QLD+d4]) = vv;
    }
    __syncthreads();

    {
        const int ww = wid & 3;
        const int j0 = (ww & 1)*16, i0 = (ww >> 1)*16;
        const float* Asrc = (wid < 4) ? qs : ks;
        float* dst = (wid < 4) ? att : Lm;
        wmma::fragment<wmma::accumulator,16,16,8,float> acc;
        wmma::fill_fragment(acc, 0.f);
        #pragma unroll 4
        for (int dk0 = 0; dk0 < 256; dk0 += 8){
            wmma::fragment<wmma::matrix_a,16,16,8,wmma::precision::tf32,wmma::row_major> af;
            wmma::load_matrix_sync(af, Asrc + i0*QLD + dk0, QLD);
            wmma::fragment<wmma::matrix_b,16,16,8,wmma::precision::tf32,wmma::col_major> bf;
            wmma::load_matrix_sync(bf, ks + j0*QLD + dk0, QLD);
            wmma::mma_sync(acc, af, bf, acc);
        }
        wmma::store_matrix_sync(dst + i0*36 + j0, acc, 36, wmma::mem_row_major);
    }
    __syncthreads();

    for (int idx = tid; idx < 1024; idx += 256){
        int i = idx>>5, j = idx&31;
        attn[(size_t)blockIdx.x*1024 + idx] = (j <= i) ? tf32r(att[i*36+j]) : 0.f;
        Lm[i*36+j] = (j < i) ? bs[i]*Lm[i*36+j] : 0.f;
    }
    __syncthreads();

    if (wid == 0){
        for (int i=0;i<32;i++){
            float xv = (lane==i) ? 1.f : 0.f;
            for (int p=0;p<i;p++) xv = fmaf(-Lm[i*36+p], Ti[p*36+lane], xv);
            Ti[i*36+lane] = xv;
            __syncwarp();
        }
    }
    __syncthreads();

    for (int idx = tid; idx < 1024; idx += 256){
        int i = idx>>5, j = idx&31;
        float t = Ti[i*36+j];
        Lm[i*36+j]  = tf32r(t);
        att[i*36+j] = -tf32r(t*bs[j]);
    }
    __syncthreads();

    #pragma unroll
    for (int t = 0; t < 8; t++){
        const int id = wid*8 + t;
        const bool isU = id < 32;
        const int tile = isU ? id : id - 32;
        const int i0 = (tile & 1)*16;
        const int j0 = (tile >> 1)*16;
        const float* A = isU ? Lm : att;
        const float* B = isU ? vs : ks;
        wmma::fragment<wmma::accumulator,16,16,8,float> acc;
        wmma::fill_fragment(acc, 0.f);
        #pragma unroll
        for (int m0 = 0; m0 < 32; m0 += 8){
            wmma::fragment<wmma::matrix_a,16,16,8,wmma::precision::tf32,wmma::row_major> af;
            wmma::load_matrix_sync(af, A + i0*36 + m0, 36);
            wmma::fragment<wmma::matrix_b,16,16,8,wmma::precision::tf32,wmma::row_major> bf;
            wmma::load_matrix_sync(bf, B + m0*QLD + j0, QLD);
            wmma::mma_sync(acc, af, bf, acc);
        }
        if (isU)
            wmma::store_matrix_sync(u + (base+i0)*256 + j0, acc, 256, wmma::mem_row_major);
        else
            wmma::store_matrix_sync(qs + i0*QLD + j0, acc, QLD, wmma::mem_row_major);
    }
    __syncthreads();

    for (int idx = tid; idx < 32*64; idx += 256){
        int i = idx>>6, d4 = (idx&63)*4;
        float4 vv = *reinterpret_cast<float4*>(&qs[i*QLD+d4]);
        vv.x = tf32r(vv.x); vv.y = tf32r(vv.y); vv.z = tf32r(vv.z); vv.w = tf32r(vv.w);
        *reinterpret_cast<float4*>(&w[(base+i)*256 + d4]) = vv;
    }
}

// ---------------- fused: delta-scan (0-127) + dual EMA (128-143) ----
// Fragment-level hi/lo splits; 2 syncthreads per chunk.
__global__ void scan_ema_kernel(const float* __restrict__ q, const float* __restrict__ k,
                                const float* __restrict__ u, const float* __restrict__ w,
                                const float* __restrict__ attn, float* __restrict__ o,
                                const float* __restrict__ v, const float* __restrict__ gs,
                                const float* __restrict__ gl,
                                float* __restrict__ es, float* __restrict__ el)
{
    if (blockIdx.x >= 128){
        const int bh = blockIdx.x - 128;
        const int dv = threadIdx.x;
        const size_t vbase = (size_t)bh*Lq*256 + dv;
        const float* gsp = gs + (size_t)bh*Lq;
        const float* glp = gl + (size_t)bh*Lq;
        float ss = 0.f, sl = 0.f;
        #pragma unroll 8
        for (int t=0;t<Lq;t++){
            float vv = v[vbase + (size_t)t*256];
            float a = gsp[t], b2 = glp[t];
            ss = fmaf(a, ss, (1.f-a)*vv);
            sl = fmaf(b2, sl, (1.f-b2)*vv);
            es[vbase + (size_t)t*256] = ss;
            el[vbase + (size_t)t*256] = sl;
        }
        return;
    }

    extern __shared__ float sm[];
    float* S   = sm;                  // fp32 master
    float* Shi = S   + 256*SLD;
    float* Slo = Shi + 256*SLD;
    float* uhh = Slo + 256*SLD;       // 32x36
    float* uhl = uhh + 32*SLD;
    const int bh = blockIdx.x >> 3;
    const int d0 = (blockIdx.x & 7) * 32;
    const int tid = threadIdx.x, warp = tid >> 5;

    for (int i = tid; i < SCAN_SMEM_FLOATS; i += 256) sm[i] = 0.f;
    __syncthreads();

    wmma::fragment<wmma::accumulator,16,16,8,float> acc2;

    for (int c = 0; c < NCHK; ++c){
        const size_t base = (size_t)bh*Lq + (size_t)c*32;
        const float* qg = q + base*256;
        const float* kg = k + base*256;
        const float* wg = w + base*256;
        const float* ug = u + base*256 + d0;
        const float* ag = attn + ((size_t)bh*NCHK + c)*1024;
        float*       og = o + base*256 + d0;

        if (warp < 4){
            // uh = u + wneg @ (Shi + Slo); split into uhh/uhl at fragment level
            const int i0 = (warp & 1)*16, j0 = (warp >> 1)*16;
            wmma::fragment<wmma::accumulator,16,16,8,float> acc;
            wmma::load_matrix_sync(acc, ug + (size_t)i0*256 + j0, 256, wmma::mem_row_major);
            #pragma unroll 4
            for (int dk0 = 0; dk0 < 256; dk0 += 8){
                wmma::fragment<wmma::matrix_a,16,16,8,wmma::precision::tf32,wmma::row_major> af;
                wmma::load_matrix_sync(af, wg + (size_t)i0*256 + dk0, 256);
                wmma::fragment<wmma::matrix_b,16,16,8,wmma::precision::tf32,wmma::row_major> bf;
                wmma::load_matrix_sync(bf, Shi + dk0*SLD + j0, SLD);
                wmma::mma_sync(acc, af, bf, acc);
                wmma::load_matrix_sync(bf, Slo + dk0*SLD + j0, SLD);
                wmma::mma_sync(acc, af, bf, acc);
            }
            wmma::fragment<wmma::accumulator,16,16,8,float> ahi, alo;
            #pragma unroll
            for (int t=0;t<acc.num_elements;t++){
                float s = acc.x[t];
                float hi = __uint_as_float(__float_as_uint(s) & 0xFFFFE000u);
                ahi.x[t] = hi;
                alo.x[t] = tf32r(s - hi);
            }
            wmma::store_matrix_sync(uhh + i0*SLD + j0, ahi, SLD, wmma::mem_row_major);
            wmma::store_matrix_sync(uhl + i0*SLD + j0, alo, SLD, wmma::mem_row_major);
        } else {
            // q @ Shi (output path)
            const int i0 = ((warp-4) & 1)*16, j0 = ((warp-4) >> 1)*16;
            wmma::fill_fragment(acc2, 0.f);
            #pragma unroll 4
            for (int dk0 = 0; dk0 < 256; dk0 += 8){
                wmma::fragment<wmma::matrix_a,16,16,8,wmma::precision::tf32,wmma::row_major> af;
                wmma::load_matrix_sync(af, qg + (size_t)i0*256 + dk0, 256);
                wmma::fragment<wmma::matrix_b,16,16,8,wmma::precision::tf32,wmma::row_major> bf;
                wmma::load_matrix_sync(bf, Shi + dk0*SLD + j0, SLD);
                wmma::mma_sync(acc2, af, bf, acc2);
            }
        }
        __syncthreads();

        if (warp < 4){
            // S += k^T @ (uhh + uhl); write S, Shi, Slo from registers
            #pragma unroll
            for (int t = 0; t < 8; t++){
                const int id = warp*8 + t;
                const int dk0 = (id >> 1)*16, j0 = (id & 1)*16;
                wmma::fragment<wmma::accumulator,16,16,8,float> acc;
                wmma::load_matrix_sync(acc, S + dk0*SLD + j0, SLD, wmma::mem_row_major);
                #pragma unroll
                for (int i2 = 0; i2 < 32; i2 += 8){
                    wmma::fragment<wmma::matrix_a,16,16,8,wmma::precision::tf32,wmma::col_major> af;
                    wmma::load_matrix_sync(af, kg + (size_t)i2*256 + dk0, 256);
                    wmma::fragment<wmma::matrix_b,16,16,8,wmma::precision::tf32,wmma::row_major> bf;
                    wmma::load_matrix_sync(bf, uhh + i2*SLD + j0, SLD);
                    wmma::mma_sync(acc, af, bf, acc);
                    wmma::load_matrix_sync(bf, uhl + i2*SLD + j0, SLD);
                    wmma::mma_sync(acc, af, bf, acc);
                }
                wmma::store_matrix_sync(S + dk0*SLD + j0, acc, SLD, wmma::mem_row_major);
                wmma::fragment<wmma::accumulator,16,16,8,float> ahi, alo;
                #pragma unroll
                for (int tt=0;tt<acc.num_elements;tt++){
                    float s = acc.x[tt];
                    float hi = __uint_as_float(__float_as_uint(s) & 0xFFFFE000u);
                    ahi.x[tt] = hi;
                    alo.x[tt] = tf32r(s - hi);
                }
                wmma::store_matrix_sync(Shi + dk0*SLD + j0, ahi, SLD, wmma::mem_row_major);
                wmma::store_matrix_sync(Slo + dk0*SLD + j0, alo, SLD, wmma::mem_row_major);
            }
        } else {
            // o = q@Shi + attn @ (uhh + uhl)
            const int i0 = ((warp-4) & 1)*16, j0 = ((warp-4) >> 1)*16;
            #pragma unroll
            for (int i2 = 0; i2 < 32; i2 += 8){
                wmma::fragment<wmma::matrix_a,16,16,8,wmma::precision::tf32,wmma::row_major> af;
                wmma::load_matrix_sync(af, ag + i0*32 + i2, 32);
                wmma::fragment<wmma::matrix_b,16,16,8,wmma::precision::tf32,wmma::row_major> bf;
                wmma::load_matrix_sync(bf, uhh + i2*SLD + j0, SLD);
                wmma::mma_sync(acc2, af, bf, acc2);
                wmma::load_matrix_sync(bf, uhl + i2*SLD + j0, SLD);
                wmma::mma_sync(acc2, af, bf, acc2);
            }
            wmma::store_matrix_sync(og + (size_t)i0*256 + j0, acc2, 256, wmma::mem_row_major);
        }
        __syncthreads();
    }
}

// ---------------- gate heads: 2 rows per warp, weights in smem --------------
__global__ void gate_head_kernel(const float* __restrict__ z,
                                 const float* __restrict__ Wc, const float* __restrict__ bc,
                                 const float* __restrict__ Wl, const float* __restrict__ bl,
                                 const float* __restrict__ Wg, const float* __restrict__ bg,
                                 const float* __restrict__ ltc, const float* __restrict__ ltf,
                                 float* __restrict__ wgt)
{
    extern __shared__ float Ws[];
    const int tid = threadIdx.x, lane = tid&31, warp = tid>>5;
    for (int idx = tid; idx < 24*128; idx += 256){
        int r = idx >> 7, c4 = (idx & 127)*4;
        const float* src = (r<8) ? Wc + r*512 + c4 :
                           (r<16)? Wl + (r-8)*512 + c4 : Wg + (r-16)*512 + c4;
        *reinterpret_cast<float4*>(&Ws[r*512 + c4]) = *reinterpret_cast<const float4*>(src);
    }
    __syncthreads();

    #pragma unroll
    for (int rr=0; rr<2; rr++){
        const int row = blockIdx.x*16 + warp*2 + rr;
        const float* zr = z + (size_t)row*512;
        float acc[24];
        #pragma unroll
        for (int r=0;r<24;r++) acc[r]=0.f;
        for (int j=lane; j<512; j+=32){
            float zv = zr[j];
            #pragma unroll
            for (int r=0;r<24;r++) acc[r] = fmaf(zv, Ws[r*512+j], acc[r]);
        }
        #pragma unroll
        for (int r=0;r<24;r++) acc[r] = warp_sum(acc[r]);

        if (lane < 4){
            const int h = lane;
            float tc = log1pf(expf(ltc[h])) + 1e-4f;
            float tf = log1pf(expf(ltf[h])) + 1e-4f;
            float c0 = acc[2*h]+bc[2*h],      c1 = acc[2*h+1]+bc[2*h+1];
            float l0 = acc[8+2*h]+bl[2*h],    l1 = acc[8+2*h+1]+bl[2*h+1];
            float g0 = acc[16+2*h]+bg[2*h],   g1 = acc[16+2*h+1]+bg[2*h+1];
            float pg0 = sigm((c0-c1)/tc), pg1 = 1.f - pg0;
            float q0  = sigm((l0-l1)/tf), q1 = 1.f - q0;
            float r0  = sigm((g0-g1)/tf), r1 = 1.f - r0;
            size_t o = (size_t)row*16 + h*4;
            wgt[o+0] = pg0*q0; wgt[o+1] = pg0*q1; wgt[o+2] = pg1*r0; wgt[o+3] = pg1*r1;
        }
    }
}

// ---------------- mix + per-head RMSNorm (rounds omix to tf32) --------------
__global__ void combine_kernel(const float* __restrict__ v, const float* __restrict__ es,
                               const float* __restrict__ el, const float* __restrict__ dl,
                               const float* __restrict__ wgt, const float* __restrict__ onw,
                               float* __restrict__ omix)
{
    const int gw = blockIdx.x*8 + (threadIdx.x>>5);
    const int row = gw >> 2, h = gw & 3;
    const int b = row >> 12, l = row & (Lq-1);
    const int lane = threadIdx.x & 31;
    const size_t gbase = ((size_t)(b*4+h)*Lq + l)*256;
    const float* wp = wgt + (size_t)row*16 + h*4;
    const float w0 = wp[0], w1 = wp[1], w2 = wp[2], w3 = wp[3];

    float4 vals[2];
    float ss = 0.f;
    #pragma unroll
    for (int s=0;s<2;s++){
        const int d = lane*4 + s*128;
        float4 a = *reinterpret_cast<const float4*>(v  + gbase + d);
        float4 b4= *reinterpret_cast<const float4*>(es + gbase + d);
        float4 c4= *reinterpret_cast<const float4*>(dl + gbase + d);
        float4 d4= *reinterpret_cast<const float4*>(el + gbase + d);
        float* av=(float*)&a; float* bv=(float*)&b4; float* cv=(float*)&c4; float* dv=(float*)&d4;
        float* ov=(float*)&vals[s];
        #pragma unroll
        for (int j=0;j<4;j++){
            float val = w0*av[j] + w1*bv[j] + w2*cv[j] + w3*dv[j];
            ov[j] = val;
            ss = fmaf(val, val, ss);
        }
    }
    ss = warp_sum(ss);
    const float rms = rsqrtf(ss*(1.f/256.f) + 1e-5f);
    float* op = omix + (size_t)row*1024 + h*256;
    #pragma unroll
    for (int s=0;s<2;s++){
        const int d = lane*4 + s*128;
        float4 w4 = *reinterpret_cast<const float4*>(onw + d);
        float* wv=(float*)&w4; float* ov=(float*)&vals[s];
        float4 r;
        float* rv=(float*)&r;
        #pragma unroll
        for (int j=0;j<4;j++) rv[j] = tf32r(ov[j]*rms*wv[j]);
        *reinterpret_cast<float4*>(op + d) = r;
    }
}

// ---------------- host ----------------
extern "C" void kernel_launch(void* const* d_in, const int* in_sizes, int n_in,
                              void* d_out, int out_size)
{
    const float* x      = (const float*)d_in[0];
    const float* Wq     = (const float*)d_in[1];
    const float* Wk     = (const float*)d_in[2];
    const float* Wv     = (const float*)d_in[3];
    const float* cqw    = (const float*)d_in[4];
    const float* ckw    = (const float*)d_in[5];
    const float* cvw    = (const float*)d_in[6];
    const float* Wb     = (const float*)d_in[7];
    const float* Wds    = (const float*)d_in[8];
    const float* bds    = (const float*)d_in[9];
    const float* Wdl    = (const float*)d_in[10];
    const float* bdl    = (const float*)d_in[11];
    const float* Wtrunk = (const float*)d_in[12];
    const float* btrunk = (const float*)d_in[13];
    const float* Wcoarse= (const float*)d_in[14];
    const float* bcoarse= (const float*)d_in[15];
    const float* Wlocal = (const float*)d_in[16];
    const float* blocal = (const float*)d_in[17];
    const float* Wglobal= (const float*)d_in[18];
    const float* bglobal= (const float*)d_in[19];
    const float* ltc    = (const float*)d_in[20];
    const float* ltf    = (const float*)d_in[21];
    const float* onw    = (const float*)d_in[22];
    const float* Wo     = (const float*)d_in[23];
    float* out = (float*)d_out;

    float* arena;
    cudaGetSymbolAddress((void**)&arena, g_arena);
    float* qpre = arena + OFF_QPRE;
    float* kpre = arena + OFF_KPRE;
    float* vpre = arena + OFF_VPRE;
    float* qb   = arena + OFF_Q;
    float* kb   = arena + OFF_K;
    float* vb   = arena + OFF_V;
    float* ub   = arena + OFF_U;
    float* wb   = arena + OFF_W;
    float* dlt  = arena + OFF_DELTA;
    float* emas = arena + OFF_EMAS;
    float* emal = arena + OFF_EMAL;
    float* omix = arena + OFF_OMIX;
    float* zb   = arena + OFF_Z;
    float* attn = arena + OFF_ATTN;
    float* beta = arena + OFF_BETA;
    float* gs   = arena + OFF_GS;
    float* gl   = arena + OFF_GL;
    float* wgt  = arena + OFF_WGT;
    float* xr   = arena + OFF_XR;
    float* WqR  = arena + OFF_WQR;
    float* WkR  = arena + OFF_WKR;
    float* WvR  = arena + OFF_WVR;
    float* WtR  = arena + OFF_WTR;
    float* WoR  = arena + OFF_WOR;

    cudaFuncSetAttribute(megagemm_kernel,  cudaFuncAttributeMaxDynamicSharedMemorySize, GEMM_SMEM_BYTES);
    cudaFuncSetAttribute(gemm_tf32_kernel, cudaFuncAttributeMaxDynamicSharedMemorySize, GEMM_SMEM_BYTES);
    cudaFuncSetAttribute(chunk_pre_kernel, cudaFuncAttributeMaxDynamicSharedMemorySize, PRE_SMEM_BYTES);
    cudaFuncSetAttribute(scan_ema_kernel,  cudaFuncAttributeMaxDynamicSharedMemorySize, SCAN_SMEM_BYTES);
    cudaFuncSetAttribute(gate_head_kernel, cudaFuncAttributeMaxDynamicSharedMemorySize, GATE_SMEM_BYTES);
    cudaFuncSetAttribute(smallproj_kernel, cudaFuncAttributeMaxDynamicSharedMemorySize, SP_SMEM_BYTES);

    dim3 blk(256);

    // 0: round x
    round_x_kernel<<<16384, blk>>>(x, xr);

    // 1: round weights
    round_w_kernel<<<4608, blk>>>(Wq, WqR, Wk, WkR, Wv, WvR, Wtrunk, WtR, Wo, WoR);

    // 2: beta / decays
    smallproj_kernel<<<MROWS/16, blk, SP_SMEM_BYTES>>>(x, Wb, Wds, bds, Wdl, bdl, beta, gs, gl);

    // 3: fused Q/K/V/trunk projections  (profiled slot)
    megagemm_kernel<<<dim3(56, MROWS/GBM), blk, GEMM_SMEM_BYTES>>>(
        xr, WqR, WkR, WvR, WtR, btrunk, qpre, kpre, vpre, zb);

    // 4: conv + silu + relayout
    conv_silu_kernel<<<MROWS, blk>>>(qpre, kpre, vpre, cqw, ckw, cvw, qb, kb, vb);

    // 5: delta rule precompute
    chunk_pre_kernel<<<2048, blk, PRE_SMEM_BYTES>>>(qb, kb, vb, beta, ub, wb, attn);

    // 6: fused scan + EMA
    scan_ema_kernel<<<144, blk, SCAN_SMEM_BYTES>>>(qb, kb, ub, wb, attn, dlt,
                                                   vb, gs, gl, emas, emal);

    // 7: gate heads
    gate_head_kernel<<<MROWS/16, blk, GATE_SMEM_BYTES>>>(zb, Wcoarse, bcoarse, Wlocal, blocal,
                                                         Wglobal, bglobal, ltc, ltf, wgt);

    // 8: combine + RMSNorm
    combine_kernel<<<MROWS/2, blk>>>(vb, emas, emal, dlt, wgt, onw, omix);

    // 9: output projection
    gemm_tf32_kernel<<<dim3(1024/GBN, MROWS/GBM), blk, GEMM_SMEM_BYTES>>>(omix, WoR, out, 1024, 1024);
}

// round 15
// speedup vs baseline: 1.0268x; 1.0062x over previous
#include <cuda_runtime.h>
#include <math.h>
#include <mma.h>

using namespace nvcuda;

#define Hq   4
#define Lq   4096
#define Dq   1024
#define CHK  32
#define NCHK 128
#define MROWS 16384

// ---------------- scratch arena ----------------
constexpr size_t SZf      = 16777216ull;
constexpr size_t OFF_QPRE = 0;
constexpr size_t OFF_KPRE = SZf;
constexpr size_t OFF_VPRE = 2*SZf;
constexpr size_t OFF_DELTA= 2*SZf;               // dlt written after vpre consumed
constexpr size_t OFF_Q    = 3*SZf;
constexpr size_t OFF_K    = 4*SZf;
constexpr size_t OFF_V    = 5*SZf;
constexpr size_t OFF_EMAS = 6*SZf;
constexpr size_t OFF_EMAL = 7*SZf;
constexpr size_t OFF_OMIX = 8*SZf;
constexpr size_t OFF_Z    = 9*SZf;
constexpr size_t OFF_ATTN = OFF_Z + 8388608ull;
constexpr size_t OFF_BETA = OFF_ATTN + 2097152ull;
constexpr size_t OFF_GS   = OFF_BETA + 65536ull;
constexpr size_t OFF_GL   = OFF_GS + 65536ull;
constexpr size_t OFF_WGT  = OFF_GL + 65536ull;
constexpr size_t OFF_XR   = OFF_WGT + 262144ull;
constexpr size_t OFF_WQR  = OFF_XR + SZf;
constexpr size_t OFF_WKR  = OFF_WQR + 1048576ull;
constexpr size_t OFF_WVR  = OFF_WKR + 1048576ull;
constexpr size_t OFF_WTR  = OFF_WVR + 1048576ull;
constexpr size_t OFF_WOR  = OFF_WTR + 524288ull;
constexpr size_t OFF_UB   = OFF_WOR + 1048576ull;   // dedicated u (NO aliasing with qpre)
constexpr size_t OFF_WB   = OFF_UB + SZf;           // dedicated w (NO aliasing with kpre)
constexpr size_t ARENA_TOTAL = OFF_WB + SZf;

__device__ float g_arena[ARENA_TOTAL];

// chunk_pre smem: qs,ks,vs (32x264) + halo (35x264) + att,Lm,Ti (32x36) + bs
constexpr int QLD = 264;
constexpr int PRE_SMEM_FLOATS = 3*32*QLD + 35*QLD + 3*32*36 + 32;  // 38072
constexpr int PRE_SMEM_BYTES  = PRE_SMEM_FLOATS*4;                 // 152288

// scan smem
constexpr int SLD = 36;
constexpr int SCAN_SMEM_FLOATS = 3*256*SLD + 2*32*SLD;
constexpr int SCAN_SMEM_BYTES  = SCAN_SMEM_FLOATS * 4;    // 119808

// GEMM tiling
constexpr int GBM = 128, GBN = 64, GBK = 32, GAP = 36;
constexpr int GSTAGE = (GBM+GBN)*GAP;
constexpr int GEMM_SMEM_BYTES = 2*GSTAGE*4;

constexpr int GATE_SMEM_BYTES = 24*512*4;
constexpr int SP_SMEM_BYTES   = 12*1024*4;

__device__ __forceinline__ float sigm(float x){ return 1.f/(1.f+expf(-x)); }
__device__ __forceinline__ float silu(float x){ return x/(1.f+expf(-x)); }
__device__ __forceinline__ float tf32r(float x){ return wmma::__float_to_tf32(x); }

__device__ __forceinline__ float warp_sum(float v){
    #pragma unroll
    for (int o=16;o>0;o>>=1) v += __shfl_xor_sync(0xffffffffu, v, o);
    return v;
}

__device__ __forceinline__ void cp16(float* s, const float* g){
    unsigned a = (unsigned)__cvta_generic_to_shared(s);
    asm volatile("cp.async.cg.shared.global [%0], [%1], 16;" :: "r"(a), "l"(g));
}

// ---------------- tf32 rounding: x ----------------
__global__ void round_x_kernel(const float* __restrict__ src, float* __restrict__ dst)
{
    int i = blockIdx.x*256 + threadIdx.x;
    float4 v = reinterpret_cast<const float4*>(src)[i];
    v.x = tf32r(v.x); v.y = tf32r(v.y); v.z = tf32r(v.z); v.w = tf32r(v.w);
    reinterpret_cast<float4*>(dst)[i] = v;
}

// ---------------- tf32 rounding: weights ----------------
__global__ void round_w_kernel(const float* __restrict__ Wq, float* __restrict__ WqR,
                               const float* __restrict__ Wk, float* __restrict__ WkR,
                               const float* __restrict__ Wv, float* __restrict__ WvR,
                               const float* __restrict__ Wt, float* __restrict__ WtR,
                               const float* __restrict__ Wo, float* __restrict__ WoR)
{
    long i = (long)blockIdx.x*256 + threadIdx.x;
    const float* src; float* dst; long off;
    if (i < 262144)               { src=Wq; dst=WqR; off=i; }
    else if (i < 2*262144)        { src=Wk; dst=WkR; off=i-262144; }
    else if (i < 3*262144)        { src=Wv; dst=WvR; off=i-2*262144; }
    else if (i < 3*262144+131072) { src=Wt; dst=WtR; off=i-3*262144; }
    else if (i < 4*262144+131072) { src=Wo; dst=WoR; off=i-3*262144-131072; }
    else return;
    float4 v = reinterpret_cast<const float4*>(src)[off];
    v.x = tf32r(v.x); v.y = tf32r(v.y); v.z = tf32r(v.z); v.w = tf32r(v.w);
    reinterpret_cast<float4*>(dst)[off] = v;
}

// ---------------- GEMM core ------------
__device__ __forceinline__ void gemm_body(const float* __restrict__ A, const float* __restrict__ W,
                                          const float* __restrict__ bias, float* __restrict__ C,
                                          int N, int K, int act, int m0, int n0, float* smem)
{
    const int tid = threadIdx.x, warp = tid>>5;
    const int tr = warp>>1, tcw = warp&1;
    const int lr = tid>>3, lc = (tid&7)*4;

    wmma::fragment<wmma::accumulator,16,16,8,float> acc[2][2];
    #pragma unroll
    for(int i=0;i<2;i++)
        #pragma unroll
        for(int j=0;j<2;j++) wmma::fill_fragment(acc[i][j], 0.f);

    const int KT = K/GBK;

    {
        float* As = smem;
        float* Ws = As + GBM*GAP;
        #pragma unroll
        for (int s=0;s<4;s++){
            int r = lr + s*32;
            cp16(&As[r*GAP+lc], &A[(size_t)(m0+r)*K + lc]);
        }
        #pragma unroll
        for (int s=0;s<2;s++){
            int r = lr + s*32;
            cp16(&Ws[r*GAP+lc], &W[(size_t)(n0+r)*K + lc]);
        }
        asm volatile("cp.async.commit_group;");
    }

    int buf = 0;
    for (int it=0; it<KT; ++it){
        if (it+1 < KT){
            float* As = smem + (buf^1)*GSTAGE;
            float* Ws = As + GBM*GAP;
            const int k0 = (it+1)*GBK;
            #pragma unroll
            for (int s=0;s<4;s++){
                int r = lr + s*32;
                cp16(&As[r*GAP+lc], &A[(size_t)(m0+r)*K + k0 + lc]);
            }
            #pragma unroll
            for (int s=0;s<2;s++){
                int r = lr + s*32;
                cp16(&Ws[r*GAP+lc], &W[(size_t)(n0+r)*K + k0 + lc]);
            }
            asm volatile("cp.async.commit_group;");
            asm volatile("cp.async.wait_group 1;");
        } else {
            asm volatile("cp.async.wait_group 0;");
        }
        __syncthreads();

        float* As = smem + buf*GSTAGE;
        float* Ws = As + GBM*GAP;
        #pragma unroll
        for (int kk=0; kk<GBK; kk+=8){
            wmma::fragment<wmma::matrix_a,16,16,8,wmma::precision::tf32,wmma::row_major> af[2];
            wmma::fragment<wmma::matrix_b,16,16,8,wmma::precision::tf32,wmma::col_major> bf[2];
            #pragma unroll
            for (int i=0;i<2;i++)
                wmma::load_matrix_sync(af[i], &As[(tr*32+i*16)*GAP + kk], GAP);
            #pragma unroll
            for (int j=0;j<2;j++)
                wmma::load_matrix_sync(bf[j], &Ws[(tcw*32+j*16)*GAP + kk], GAP);
            #pragma unroll
            for (int i=0;i<2;i++)
                #pragma unroll
                for (int j=0;j<2;j++)
                    wmma::mma_sync(acc[i][j], af[i], bf[j], acc[i][j]);
        }
        __syncthreads();
        buf ^= 1;
    }

    if (!bias && act == 0){
        #pragma unroll
        for (int i=0;i<2;i++)
            #pragma unroll
            for (int j=0;j<2;j++)
                wmma::store_matrix_sync(&C[(size_t)(m0+tr*32+i*16)*N + n0 + tcw*32 + j*16],
                                        acc[i][j], N, wmma::mem_row_major);
        return;
    }

    float* Cs = smem;
    #pragma unroll
    for (int i=0;i<2;i++)
        #pragma unroll
        for (int j=0;j<2;j++)
            wmma::store_matrix_sync(&Cs[(tr*32+i*16)*72 + tcw*32 + j*16], acc[i][j], 72, wmma::mem_row_major);
    __syncthreads();

    for (int idx = tid; idx < GBM*GBN/4; idx += 256){
        int row = idx >> 4, col = (idx & 15)*4;
        float4 v4 = *reinterpret_cast<float4*>(&Cs[row*72 + col]);
        float* vv = (float*)&v4;
        #pragma unroll
        for (int j=0;j<4;j++){
            float v = vv[j];
            if (bias) v += bias[n0+col+j];
            if (act==1) v = v/(1.f+expf(-v));
            vv[j] = v;
        }
        *reinterpret_cast<float4*>(&C[(size_t)(m0+row)*N + n0+col]) = v4;
    }
}

// ---------------- mega GEMM ----------
__global__ void __launch_bounds__(256, 4)
megagemm_kernel(const float* __restrict__ x,
                const float* __restrict__ Wq, const float* __restrict__ Wk,
                const float* __restrict__ Wv, const float* __restrict__ Wt,
                const float* __restrict__ bt,
                float* __restrict__ qpre, float* __restrict__ kpre,
                float* __restrict__ vpre, float* __restrict__ zb)
{
    extern __shared__ float smem[];
    const int bx = blockIdx.x;
    const int m0 = blockIdx.y*GBM;
    const float* W; float* C; const float* bias = nullptr;
    int N, act = 0, nb;
    if (bx < 16)      { W = Wq; C = qpre; N = 1024; nb = bx; }
    else if (bx < 32) { W = Wk; C = kpre; N = 1024; nb = bx-16; }
    else if (bx < 48) { W = Wv; C = vpre; N = 1024; nb = bx-32; }
    else              { W = Wt; C = zb;   N = 512;  nb = bx-48; bias = bt; act = 1; }
    gemm_body(x, W, bias, C, N, 1024, act, m0, nb*GBN, smem);
}

__global__ void __launch_bounds__(256, 4)
gemm_tf32_kernel(const float* __restrict__ A, const float* __restrict__ W,
                 float* __restrict__ C, int N, int K)
{
    extern __shared__ float smem[];
    gemm_body(A, W, nullptr, C, N, K, 0, blockIdx.y*GBM, blockIdx.x*GBN, smem);
}

// ---------------- beta/gs/gl ----------------
__global__ void smallproj_kernel(const float* __restrict__ x,
                                 const float* __restrict__ Wb, const float* __restrict__ Wds,
                                 const float* __restrict__ bds, const float* __restrict__ Wdl,
                                 const float* __restrict__ bdl,
                                 float* __restrict__ beta, float* __restrict__ gs,
                                 float* __restrict__ gl)
{
    extern __shared__ float Ws[];
    const int tid = threadIdx.x, lane = tid&31, warp = tid>>5;
    for (int idx = tid; idx < 12*256; idx += 256){
        int r = idx >> 8, c4 = (idx & 255)*4;
        const float* src = (r<4) ? Wb + r*1024 + c4 :
                           (r<8) ? Wds + (r-4)*1024 + c4 : Wdl + (r-8)*1024 + c4;
        *reinterpret_cast<float4*>(&Ws[r*1024 + c4]) = *reinterpret_cast<const float4*>(src);
    }
    __syncthreads();

    #pragma unroll
    for (int rr=0; rr<2; rr++){
        const int row = blockIdx.x*16 + warp*2 + rr;
        const float* xr = x + (size_t)row*Dq;
        float acc[12];
        #pragma unroll
        for (int r=0;r<12;r++) acc[r]=0.f;
        #pragma unroll
        for (int it=0; it<8; it++){
            const int j = it*128 + lane*4;
            float4 xv4 = *reinterpret_cast<const float4*>(xr + j);
            const float* xv = (const float*)&xv4;
            #pragma unroll
            for (int r=0;r<12;r++){
                float a = acc[r];
                a = fmaf(xv[0], Ws[r*1024+j],   a);
                a = fmaf(xv[1], Ws[r*1024+j+1], a);
                a = fmaf(xv[2], Ws[r*1024+j+2], a);
                a = fmaf(xv[3], Ws[r*1024+j+3], a);
                acc[r] = a;
            }
        }
        #pragma unroll
        for (int r=0;r<12;r++) acc[r] = warp_sum(acc[r]);

        if (lane < 12){
            const int h = lane & 3;
            const int b = row >> 12, l = row & (Lq-1);
            size_t o = (size_t)(b*4 + h)*Lq + l;
            if (lane < 4)      beta[o] = sigm(acc[h]);
            else if (lane < 8) gs[o]   = sigm(acc[4+h] + bds[h]);
            else               gl[o]   = sigm(acc[8+h] + bdl[h]);
        }
    }
}

// ---------------- chunk_pre: fused conv+silu + delta precompute (wmma) -------
__global__ void chunk_pre_kernel(const float* __restrict__ qpre, const float* __restrict__ kpre,
                                 const float* __restrict__ vpre,
                                 const float* __restrict__ cqw, const float* __restrict__ ckw,
                                 const float* __restrict__ cvw,
                                 float* __restrict__ q, float* __restrict__ k,
                                 float* __restrict__ vb, const float* __restrict__ beta,
                                 float* __restrict__ u, float* __restrict__ w,
                                 float* __restrict__ attn)
{
    extern __shared__ float sm[];
    float* qs  = sm;                  // 32*264
    float* ks  = qs + 32*QLD;
    float* vs  = ks + 32*QLD;
    float* Hs  = vs + 32*QLD;         // 35*264 halo
    float* att = Hs + 35*QLD;         // 32*36
    float* Lm  = att+ 32*36;
    float* Ti  = Lm + 32*36;
    float* bs  = Ti + 32*36;
    const int bh = blockIdx.x >> 7, c = blockIdx.x & 127;
    const int b = bh >> 2, h = bh & 3;
    const int l0 = c*CHK;
    const int tid = threadIdx.x, lane = tid&31, wid = tid>>5;
    const size_t base = (size_t)bh*Lq + (size_t)l0;

    if (tid < 32) bs[tid] = beta[base + tid];

    // ---- conv + silu for q, k, v ----
    const int d4f = (tid & 63)*4;
    const int i0r = (tid >> 6)*8;
    #pragma unroll
    for (int t = 0; t < 3; t++){
        const float* P = (t==0) ? qpre : (t==1) ? kpre : vpre;
        const float* T = (t==0) ? cqw  : (t==1) ? ckw  : cvw;
        float* D = (t==0) ? qs : (t==1) ? ks : vs;

        for (int idx = tid; idx < 35*64; idx += 256){
            int jj = idx >> 6, d4 = (idx & 63)*4;
            int gl = l0 - 3 + jj;
            float4 val = make_float4(0.f,0.f,0.f,0.f);
            if (gl >= 0)
                val = *reinterpret_cast<const float4*>(P + (size_t)(b*Lq + gl)*Dq + h*256 + d4);
            *reinterpret_cast<float4*>(&Hs[jj*QLD + d4]) = val;
        }
        __syncthreads();

        float4 taps[4];
        #pragma unroll
        for (int c2=0;c2<4;c2++)
            taps[c2] = *reinterpret_cast<const float4*>(T + (h*256 + d4f + c2)*4);

        #pragma unroll
        for (int i = i0r; i < i0r+8; i++){
            float a[4] = {0.f,0.f,0.f,0.f};
            #pragma unroll
            for (int j=0;j<4;j++){
                float4 hv = *reinterpret_cast<float4*>(&Hs[(i+j)*QLD + d4f]);
                const float* hvf = (const float*)&hv;
                #pragma unroll
                for (int c2=0;c2<4;c2++)
                    a[c2] = fmaf(hvf[c2], ((const float*)&taps[c2])[j], a[c2]);
            }
            float4 o;
            float* of = (float*)&o;
            #pragma unroll
            for (int c2=0;c2<4;c2++) of[c2] = silu(a[c2]);
            *reinterpret_cast<float4*>(&D[i*QLD + d4f]) = o;
            if (t == 2)
                *reinterpret_cast<float4*>(&vb[(base+i)*256 + d4f]) = o;
        }
        __syncthreads();
    }

    // ---- l2norm rows -> round to tf32 in smem ----
    #pragma unroll
    for (int r=0;r<4;r++){
        int i = wid*4 + r;
        float sq=0.f, sk=0.f;
        for (int d=lane; d<256; d+=32){
            float a=qs[i*QLD+d]; sq=fmaf(a,a,sq);
            float bb=ks[i*QLD+d]; sk=fmaf(bb,bb,sk);
        }
        sq = warp_sum(sq); sk = warp_sum(sk);
        float rq = rsqrtf(sq + 1e-6f), rk = rsqrtf(sk + 1e-6f);
        for (int d=lane; d<256; d+=32){
            qs[i*QLD+d] = tf32r(qs[i*QLD+d]*rq);
            ks[i*QLD+d] = tf32r(ks[i*QLD+d]*rk);
        }
    }
    __syncthreads();

    for (int idx = tid; idx < 32*64; idx += 256){
        int i = idx>>6, d4 = (idx&63)*4;
        size_t g = (base+i)*256 + d4;
        *reinterpret_cast<float4*>(&q[g]) = *reinterpret_cast<float4*>(&qs[i*QLD+d4]);
        *reinterpret_cast<float4*>(&k[g]) = *reinterpret_cast<float4*>(&ks[i*QLD+d4]);
        float bb = bs[i];
        float4 vv = *reinterpret_cast<float4*>(&vs[i*QLD+d4]);
        vv.x = tf32r(vv.x*bb); vv.y = tf32r(vv.y*bb); vv.z = tf32r(vv.z*bb); vv.w = tf32r(vv.w*bb);
        *reinterpret_cast<float4*>(&vs[i*QLD+d4]) = vv;
    }
    __syncthreads();

    {
        const int ww = wid & 3;
        const int j0 = (ww & 1)*16, i0 = (ww >> 1)*16;
        const float* Asrc = (wid < 4) ? qs : ks;
        float* dst = (wid < 4) ? att : Lm;
        wmma::fragment<wmma::accumulator,16,16,8,float> acc;
        wmma::fill_fragment(acc, 0.f);
        #pragma unroll 4
        for (int dk0 = 0; dk0 < 256; dk0 += 8){
            wmma::fragment<wmma::matrix_a,16,16,8,wmma::precision::tf32,wmma::row_major> af;
            wmma::load_matrix_sync(af, Asrc + i0*QLD + dk0, QLD);
            wmma::fragment<wmma::matrix_b,16,16,8,wmma::precision::tf32,wmma::col_major> bf;
            wmma::load_matrix_sync(bf, ks + j0*QLD + dk0, QLD);
            wmma::mma_sync(acc, af, bf, acc);
        }
        wmma::store_matrix_sync(dst + i0*36 + j0, acc, 36, wmma::mem_row_major);
    }
    __syncthreads();

    for (int idx = tid; idx < 1024; idx += 256){
        int i = idx>>5, j = idx&31;
        attn[(size_t)blockIdx.x*1024 + idx] = (j <= i) ? tf32r(att[i*36+j]) : 0.f;
        Lm[i*36+j] = (j < i) ? bs[i]*Lm[i*36+j] : 0.f;
    }
    __syncthreads();

    if (wid == 0){
        for (int i=0;i<32;i++){
            float xv = (lane==i) ? 1.f : 0.f;
            for (int p=0;p<i;p++) xv = fmaf(-Lm[i*36+p], Ti[p*36+lane], xv);
            Ti[i*36+lane] = xv;
            __syncwarp();
        }
    }
    __syncthreads();

    for (int idx = tid; idx < 1024; idx += 256){
        int i = idx>>5, j = idx&31;
        float t = Ti[i*36+j];
        Lm[i*36+j]  = tf32r(t);
        att[i*36+j] = -tf32r(t*bs[j]);
    }
    __syncthreads();

    #pragma unroll
    for (int t = 0; t < 8; t++){
        const int id = wid*8 + t;
        const bool isU = id < 32;
        const int tile = isU ? id : id - 32;
        const int i0 = (tile & 1)*16;
        const int j0 = (tile >> 1)*16;
        const float* A = isU ? Lm : att;
        const float* B = isU ? vs : ks;
        wmma::fragment<wmma::accumulator,16,16,8,float> acc;
        wmma::fill_fragment(acc, 0.f);
        #pragma unroll
        for (int m0 = 0; m0 < 32; m0 += 8){
            wmma::fragment<wmma::matrix_a,16,16,8,wmma::precision::tf32,wmma::row_major> af;
            wmma::load_matrix_sync(af, A + i0*36 + m0, 36);
            wmma::fragment<wmma::matrix_b,16,16,8,wmma::precision::tf32,wmma::row_major> bf;
            wmma::load_matrix_sync(bf, B + m0*QLD + j0, QLD);
            wmma::mma_sync(acc, af, bf, acc);
        }
        if (isU)
            wmma::store_matrix_sync(u + (base+i0)*256 + j0, acc, 256, wmma::mem_row_major);
        else
            wmma::store_matrix_sync(qs + i0*QLD + j0, acc, QLD, wmma::mem_row_major);
    }
    __syncthreads();

    for (int idx = tid; idx < 32*64; idx += 256){
        int i = idx>>6, d4 = (idx&63)*4;
        float4 vv = *reinterpret_cast<float4*>(&qs[i*QLD+d4]);
        vv.x = tf32r(vv.x); vv.y = tf32r(vv.y); vv.z = tf32r(vv.z); vv.w = tf32r(vv.w);
        *reinterpret_cast<float4*>(&w[(base+i)*256 + d4]) = vv;
    }
}

// ---------------- fused: delta-scan (0-127) + dual EMA (128-143) ----
__global__ void scan_ema_kernel(const float* __restrict__ q, const float* __restrict__ k,
                                const float* __restrict__ u, const float* __restrict__ w,
                                const float* __restrict__ attn, float* __restrict__ o,
                                const float* __restrict__ v, const float* __restrict__ gs,
                                const float* __restrict__ gl,
                                float* __restrict__ es, float* __restrict__ el)
{
    if (blockIdx.x >= 128){
        const int bh = blockIdx.x - 128;
        const int dv = threadIdx.x;
        const size_t vbase = (size_t)bh*Lq*256 + dv;
        const float* gsp = gs + (size_t)bh*Lq;
        const float* glp = gl + (size_t)bh*Lq;
        float ss = 0.f, sl = 0.f;
        #pragma unroll 8
        for (int t=0;t<Lq;t++){
            float vv = v[vbase + (size_t)t*256];
            float a = gsp[t], b2 = glp[t];
            ss = fmaf(a, ss, (1.f-a)*vv);
            sl = fmaf(b2, sl, (1.f-b2)*vv);
            es[vbase + (size_t)t*256] = ss;
            el[vbase + (size_t)t*256] = sl;
        }
        return;
    }

    extern __shared__ float sm[];
    float* S   = sm;
    float* Shi = S   + 256*SLD;
    float* Slo = Shi + 256*SLD;
    float* uhh = Slo + 256*SLD;
    float* uhl = uhh + 32*SLD;
    const int bh = blockIdx.x >> 3;
    const int d0 = (blockIdx.x & 7) * 32;
    const int tid = threadIdx.x, warp = tid >> 5;

    for (int i = tid; i < SCAN_SMEM_FLOATS; i += 256) sm[i] = 0.f;
    __syncthreads();

    wmma::fragment<wmma::accumulator,16,16,8,float> acc2;

    for (int c = 0; c < NCHK; ++c){
        const size_t base = (size_t)bh*Lq + (size_t)c*32;
        const float* qg = q + base*256;
        const float* kg = k + base*256;
        const float* wg = w + base*256;
        const float* ug = u + base*256 + d0;
        const float* ag = attn + ((size_t)bh*NCHK + c)*1024;
        float*       og = o + base*256 + d0;

        if (warp < 4){
            const int i0 = (warp & 1)*16, j0 = (warp >> 1)*16;
            wmma::fragment<wmma::accumulator,16,16,8,float> acc;
            wmma::load_matrix_sync(acc, ug + (size_t)i0*256 + j0, 256, wmma::mem_row_major);
            #pragma unroll 4
            for (int dk0 = 0; dk0 < 256; dk0 += 8){
                wmma::fragment<wmma::matrix_a,16,16,8,wmma::precision::tf32,wmma::row_major> af;
                wmma::load_matrix_sync(af, wg + (size_t)i0*256 + dk0, 256);
                wmma::fragment<wmma::matrix_b,16,16,8,wmma::precision::tf32,wmma::row_major> bf;
                wmma::load_matrix_sync(bf, Shi + dk0*SLD + j0, SLD);
                wmma::mma_sync(acc, af, bf, acc);
                wmma::load_matrix_sync(bf, Slo + dk0*SLD + j0, SLD);
                wmma::mma_sync(acc, af, bf, acc);
            }
            wmma::fragment<wmma::accumulator,16,16,8,float> ahi, alo;
            #pragma unroll
            for (int t=0;t<acc.num_elements;t++){
                float s = acc.x[t];
                float hi = __uint_as_float(__float_as_uint(s) & 0xFFFFE000u);
                ahi.x[t] = hi;
                alo.x[t] = tf32r(s - hi);
            }
            wmma::store_matrix_sync(uhh + i0*SLD + j0, ahi, SLD, wmma::mem_row_major);
            wmma::store_matrix_sync(uhl + i0*SLD + j0, alo, SLD, wmma::mem_row_major);
        } else {
            const int i0 = ((warp-4) & 1)*16, j0 = ((warp-4) >> 1)*16;
            wmma::fill_fragment(acc2, 0.f);
            #pragma unroll 4
            for (int dk0 = 0; dk0 < 256; dk0 += 8){
                wmma::fragment<wmma::matrix_a,16,16,8,wmma::precision::tf32,wmma::row_major> af;
                wmma::load_matrix_sync(af, qg + (size_t)i0*256 + dk0, 256);
                wmma::fragment<wmma::matrix_b,16,16,8,wmma::precision::tf32,wmma::row_major> bf;
                wmma::load_matrix_sync(bf, Shi + dk0*SLD + j0, SLD);
                wmma::mma_sync(acc2, af, bf, acc2);
            }
        }
        __syncthreads();

        if (warp < 4){
            #pragma unroll
            for (int t = 0; t < 8; t++){
                const int id = warp*8 + t;
                const int dk0 = (id >> 1)*16, j0 = (id & 1)*16;
                wmma::fragment<wmma::accumulator,16,16,8,float> acc;
                wmma::load_matrix_sync(acc, S + dk0*SLD + j0, SLD, wmma::mem_row_major);
                #pragma unroll
                for (int i2 = 0; i2 < 32; i2 += 8){
                    wmma::fragment<wmma::matrix_a,16,16,8,wmma::precision::tf32,wmma::col_major> af;
                    wmma::load_matrix_sync(af, kg + (size_t)i2*256 + dk0, 256);
                    wmma::fragment<wmma::matrix_b,16,16,8,wmma::precision::tf32,wmma::row_major> bf;
                    wmma::load_matrix_sync(bf, uhh + i2*SLD + j0, SLD);
                    wmma::mma_sync(acc, af, bf, acc);
                    wmma::load_matrix_sync(bf, uhl + i2*SLD + j0, SLD);
                    wmma::mma_sync(acc, af, bf, acc);
                }
                wmma::store_matrix_sync(S + dk0*SLD + j0, acc, SLD, wmma::mem_row_major);
                wmma::fragment<wmma::accumulator,16,16,8,float> ahi, alo;
                #pragma unroll
                for (int tt=0;tt<acc.num_elements;tt++){
                    float s = acc.x[tt];
                    float hi = __uint_as_float(__float_as_uint(s) & 0xFFFFE000u);
                    ahi.x[tt] = hi;
                    alo.x[tt] = tf32r(s - hi);
                }
                wmma::store_matrix_sync(Shi + dk0*SLD + j0, ahi, SLD, wmma::mem_row_major);
                wmma::store_matrix_sync(Slo + dk0*SLD + j0, alo, SLD, wmma::mem_row_major);
            }
        } else {
            const int i0 = ((warp-4) & 1)*16, j0 = ((warp-4) >> 1)*16;
            #pragma unroll
            for (int i2 = 0; i2 < 32; i2 += 8){
                wmma::fragment<wmma::matrix_a,16,16,8,wmma::precision::tf32,wmma::row_major> af;
                wmma::load_matrix_sync(af, ag + i0*32 + i2, 32);
                wmma::fragment<wmma::matrix_b,16,16,8,wmma::precision::tf32,wmma::row_major> bf;
                wmma::load_matrix_sync(bf, uhh + i2*SLD + j0, SLD);
                wmma::mma_sync(acc2, af, bf, acc2);
                wmma::load_matrix_sync(bf, uhl + i2*SLD + j0, SLD);
                wmma::mma_sync(acc2, af, bf, acc2);
            }
            wmma::store_matrix_sync(og + (size_t)i0*256 + j0, acc2, 256, wmma::mem_row_major);
        }
        __syncthreads();
    }
}

// ---------------- gate heads ----------------
__global__ void gate_head_kernel(const float* __restrict__ z,
                                 const float* __restrict__ Wc, const float* __restrict__ bc,
                                 const float* __restrict__ Wl, const float* __restrict__ bl,
                                 const float* __restrict__ Wg, const float* __restrict__ bg,
                                 const float* __restrict__ ltc, const float* __restrict__ ltf,
                                 float* __restrict__ wgt)
{
    extern __shared__ float Ws[];
    const int tid = threadIdx.x, lane = tid&31, warp = tid>>5;
    for (int idx = tid; idx < 24*128; idx += 256){
        int r = idx >> 7, c4 = (idx & 127)*4;
        const float* src = (r<8) ? Wc + r*512 + c4 :
                           (r<16)? Wl + (r-8)*512 + c4 : Wg + (r-16)*512 + c4;
        *reinterpret_cast<float4*>(&Ws[r*512 + c4]) = *reinterpret_cast<const float4*>(src);
    }
    __syncthreads();

    #pragma unroll
    for (int rr=0; rr<2; rr++){
        const int row = blockIdx.x*16 + warp*2 + rr;
        const float* zr = z + (size_t)row*512;
        float acc[24];
        #pragma unroll
        for (int r=0;r<24;r++) acc[r]=0.f;
        for (int j=lane; j<512; j+=32){
            float zv = zr[j];
            #pragma unroll
            for (int r=0;r<24;r++) acc[r] = fmaf(zv, Ws[r*512+j], acc[r]);
        }
        #pragma unroll
        for (int r=0;r<24;r++) acc[r] = warp_sum(acc[r]);

        if (lane < 4){
            const int h = lane;
            float tc = log1pf(expf(ltc[h])) + 1e-4f;
            float tf = log1pf(expf(ltf[h])) + 1e-4f;
            float c0 = acc[2*h]+bc[2*h],      c1 = acc[2*h+1]+bc[2*h+1];
            float l0 = acc[8+2*h]+bl[2*h],    l1 = acc[8+2*h+1]+bl[2*h+1];
            float g0 = acc[16+2*h]+bg[2*h],   g1 = acc[16+2*h+1]+bg[2*h+1];
            float pg0 = sigm((c0-c1)/tc), pg1 = 1.f - pg0;
            float q0  = sigm((l0-l1)/tf), q1 = 1.f - q0;
            float r0  = sigm((g0-g1)/tf), r1 = 1.f - r0;
            size_t o = (size_t)row*16 + h*4;
            wgt[o+0] = pg0*q0; wgt[o+1] = pg0*q1; wgt[o+2] = pg1*r0; wgt[o+3] = pg1*r1;
        }
    }
}

// ---------------- mix + per-head RMSNorm ----------------
__global__ void combine_kernel(const float* __restrict__ v, const float* __restrict__ es,
                               const float* __restrict__ el, const float* __restrict__ dl,
                               const float* __restrict__ wgt, const float* __restrict__ onw,
                               float* __restrict__ omix)
{
    const int gw = blockIdx.x*8 + (threadIdx.x>>5);
    const int row = gw >> 2, h = gw & 3;
    const int b = row >> 12, l = row & (Lq-1);
    const int lane = threadIdx.x & 31;
    const size_t gbase = ((size_t)(b*4+h)*Lq + l)*256;
    const float* wp = wgt + (size_t)row*16 + h*4;
    const float w0 = wp[0], w1 = wp[1], w2 = wp[2], w3 = wp[3];

    float4 vals[2];
    float ss = 0.f;
    #pragma unroll
    for (int s=0;s<2;s++){
        const int d = lane*4 + s*128;
        float4 a = *reinterpret_cast<const float4*>(v  + gbase + d);
        float4 b4= *reinterpret_cast<const float4*>(es + gbase + d);
        float4 c4= *reinterpret_cast<const float4*>(dl + gbase + d);
        float4 d4= *reinterpret_cast<const float4*>(el + gbase + d);
        float* av=(float*)&a; float* bv=(float*)&b4; float* cv=(float*)&c4; float* dv=(float*)&d4;
        float* ov=(float*)&vals[s];
        #pragma unroll
        for (int j=0;j<4;j++){
            float val = w0*av[j] + w1*bv[j] + w2*cv[j] + w3*dv[j];
            ov[j] = val;
            ss = fmaf(val, val, ss);
        }
    }
    ss = warp_sum(ss);
    const float rms = rsqrtf(ss*(1.f/256.f) + 1e-5f);
    float* op = omix + (size_t)row*1024 + h*256;
    #pragma unroll
    for (int s=0;s<2;s++){
        const int d = lane*4 + s*128;
        float4 w4 = *reinterpret_cast<const float4*>(onw + d);
        float* wv=(float*)&w4; float* ov=(float*)&vals[s];
        float4 r;
        float* rv=(float*)&r;
        #pragma unroll
        for (int j=0;j<4;j++) rv[j] = tf32r(ov[j]*rms*wv[j]);
        *reinterpret_cast<float4*>(op + d) = r;
    }
}

// ---------------- host ----------------
extern "C" void kernel_launch(void* const* d_in, const int* in_sizes, int n_in,
                              void* d_out, int out_size)
{
    const float* x      = (const float*)d_in[0];
    const float* Wq     = (const float*)d_in[1];
    const float* Wk     = (const float*)d_in[2];
    const float* Wv     = (const float*)d_in[3];
    const float* cqw    = (const float*)d_in[4];
    const float* ckw    = (const float*)d_in[5];
    const float* cvw    = (const float*)d_in[6];
    const float* Wb     = (const float*)d_in[7];
    const float* Wds    = (const float*)d_in[8];
    const float* bds    = (const float*)d_in[9];
    const float* Wdl    = (const float*)d_in[10];
    const float* bdl    = (const float*)d_in[11];
    const float* Wtrunk = (const float*)d_in[12];
    const float* btrunk = (const float*)d_in[13];
    const float* Wcoarse= (const float*)d_in[14];
    const float* bcoarse= (const float*)d_in[15];
    const float* Wlocal = (const float*)d_in[16];
    const float* blocal = (const float*)d_in[17];
    const float* Wglobal= (const float*)d_in[18];
    const float* bglobal= (const float*)d_in[19];
    const float* ltc    = (const float*)d_in[20];
    const float* ltf    = (const float*)d_in[21];
    const float* onw    = (const float*)d_in[22];
    const float* Wo     = (const float*)d_in[23];
    float* out = (float*)d_out;

    float* arena;
    cudaGetSymbolAddress((void**)&arena, g_arena);
    float* qpre = arena + OFF_QPRE;
    float* kpre = arena + OFF_KPRE;
    float* vpre = arena + OFF_VPRE;
    float* qb   = arena + OFF_Q;
    float* kb   = arena + OFF_K;
    float* vb   = arena + OFF_V;
    float* ub   = arena + OFF_UB;
    float* wb   = arena + OFF_WB;
    float* dlt  = arena + OFF_DELTA;
    float* emas = arena + OFF_EMAS;
    float* emal = arena + OFF_EMAL;
    float* omix = arena + OFF_OMIX;
    float* zb   = arena + OFF_Z;
    float* attn = arena + OFF_ATTN;
    float* beta = arena + OFF_BETA;
    float* gs   = arena + OFF_GS;
    float* gl   = arena + OFF_GL;
    float* wgt  = arena + OFF_WGT;
    float* xr   = arena + OFF_XR;
    float* WqR  = arena + OFF_WQR;
    float* WkR  = arena + OFF_WKR;
    float* WvR  = arena + OFF_WVR;
    float* WtR  = arena + OFF_WTR;
    float* WoR  = arena + OFF_WOR;

    cudaFuncSetAttribute(megagemm_kernel,  cudaFuncAttributeMaxDynamicSharedMemorySize, GEMM_SMEM_BYTES);
    cudaFuncSetAttribute(gemm_tf32_kernel, cudaFuncAttributeMaxDynamicSharedMemorySize, GEMM_SMEM_BYTES);
    cudaFuncSetAttribute(chunk_pre_kernel, cudaFuncAttributeMaxDynamicSharedMemorySize, PRE_SMEM_BYTES);
    cudaFuncSetAttribute(scan_ema_kernel,  cudaFuncAttributeMaxDynamicSharedMemorySize, SCAN_SMEM_BYTES);
    cudaFuncSetAttribute(gate_head_kernel, cudaFuncAttributeMaxDynamicSharedMemorySize, GATE_SMEM_BYTES);
    cudaFuncSetAttribute(smallproj_kernel, cudaFuncAttributeMaxDynamicSharedMemorySize, SP_SMEM_BYTES);

    dim3 blk(256);

    // 0: round x
    round_x_kernel<<<16384, blk>>>(x, xr);

    // 1: round weights
    round_w_kernel<<<4608, blk>>>(Wq, WqR, Wk, WkR, Wv, WvR, Wtrunk, WtR, Wo, WoR);

    // 2: beta / decays
    smallproj_kernel<<<MROWS/16, blk, SP_SMEM_BYTES>>>(x, Wb, Wds, bds, Wdl, bdl, beta, gs, gl);

    // 3: fused Q/K/V/trunk projections  (profiled slot)
    megagemm_kernel<<<dim3(56, MROWS/GBM), blk, GEMM_SMEM_BYTES>>>(
        xr, WqR, WkR, WvR, WtR, btrunk, qpre, kpre, vpre, zb);

    // 4: fused conv+silu + delta precompute (u/w now non-aliased)
    chunk_pre_kernel<<<2048, blk, PRE_SMEM_BYTES>>>(qpre, kpre, vpre, cqw, ckw, cvw,
                                                    qb, kb, vb, beta, ub, wb, attn);

    // 5: fused scan + EMA
    scan_ema_kernel<<<144, blk, SCAN_SMEM_BYTES>>>(qb, kb, ub, wb, attn, dlt,
                                                   vb, gs, gl, emas, emal);

    // 6: gate heads
    gate_head_kernel<<<MROWS/16, blk, GATE_SMEM_BYTES>>>(zb, Wcoarse, bcoarse, Wlocal, blocal,
                                                         Wglobal, bglobal, ltc, ltf, wgt);

    // 7: combine + RMSNorm
    combine_kernel<<<MROWS/2, blk>>>(vb, emas, emal, dlt, wgt, onw, omix);

    // 8: output projection
    gemm_tf32_kernel<<<dim3(1024/GBN, MROWS/GBM), blk, GEMM_SMEM_BYTES>>>(omix, WoR, out, 1024, 1024);
}

// round 16
// speedup vs baseline: 1.0553x; 1.0277x over previous
#include <cuda_runtime.h>
#include <math.h>
#include <mma.h>

using namespace nvcuda;

#define Hq   4
#define Lq   4096
#define Dq   1024
#define CHK  32
#define NCHK 128
#define MROWS 16384

// ---------------- scratch arena ----------------
constexpr size_t SZf      = 16777216ull;
constexpr size_t OFF_QPRE = 0;
constexpr size_t OFF_KPRE = SZf;
constexpr size_t OFF_VPRE = 2*SZf;
constexpr size_t OFF_DELTA= 2*SZf;               // dlt written after vpre consumed
constexpr size_t OFF_Q    = 3*SZf;
constexpr size_t OFF_K    = 4*SZf;
constexpr size_t OFF_V    = 5*SZf;
constexpr size_t OFF_EMAS = 6*SZf;
constexpr size_t OFF_EMAL = 7*SZf;
constexpr size_t OFF_OMIX = 8*SZf;
constexpr size_t OFF_Z    = 9*SZf;
constexpr size_t OFF_ATTN = OFF_Z + 8388608ull;
constexpr size_t OFF_BETA = OFF_ATTN + 2097152ull;
constexpr size_t OFF_GS   = OFF_BETA + 65536ull;
constexpr size_t OFF_GL   = OFF_GS + 65536ull;
constexpr size_t OFF_WGT  = OFF_GL + 65536ull;
constexpr size_t OFF_XR   = OFF_WGT + 262144ull;
constexpr size_t OFF_WQR  = OFF_XR + SZf;
constexpr size_t OFF_WKR  = OFF_WQR + 1048576ull;
constexpr size_t OFF_WVR  = OFF_WKR + 1048576ull;
constexpr size_t OFF_WTR  = OFF_WVR + 1048576ull;
constexpr size_t OFF_WOR  = OFF_WTR + 524288ull;
constexpr size_t OFF_UB   = OFF_WOR + 1048576ull;   // dedicated u (NO aliasing with qpre)
constexpr size_t OFF_WB   = OFF_UB + SZf;           // dedicated w (NO aliasing with kpre)
constexpr size_t ARENA_TOTAL = OFF_WB + SZf;

__device__ float g_arena[ARENA_TOTAL];

// chunk_pre smem
constexpr int QLD = 264;
constexpr int PRE_SMEM_FLOATS = 3*32*QLD + 35*QLD + 3*32*36 + 32;
constexpr int PRE_SMEM_BYTES  = PRE_SMEM_FLOATS*4;                 // 152288

// scan smem
constexpr int SLD = 36;
constexpr int SCAN_SMEM_FLOATS = 3*256*SLD + 2*32*SLD;
constexpr int SCAN_SMEM_BYTES  = SCAN_SMEM_FLOATS * 4;    // 119808

// GEMM tiling
constexpr int GBM = 128, GBN = 64, GBK = 32, GAP = 36;
constexpr int GSTAGE = (GBM+GBN)*GAP;
constexpr int GEMM_SMEM_BYTES = 2*GSTAGE*4;

constexpr int GATE_SMEM_BYTES = 24*512*4;
constexpr int SP_SMEM_BYTES   = 12*1024*4;

__device__ __forceinline__ float sigm(float x){ return 1.f/(1.f+expf(-x)); }
__device__ __forceinline__ float silu(float x){ return x/(1.f+expf(-x)); }
__device__ __forceinline__ float tf32r(float x){ return wmma::__float_to_tf32(x); }

__device__ __forceinline__ float warp_sum(float v){
    #pragma unroll
    for (int o=16;o>0;o>>=1) v += __shfl_xor_sync(0xffffffffu, v, o);
    return v;
}

__device__ __forceinline__ void cp16(float* s, const float* g){
    unsigned a = (unsigned)__cvta_generic_to_shared(s);
    asm volatile("cp.async.cg.shared.global [%0], [%1], 16;" :: "r"(a), "l"(g));
}

// ---------------- fused tf32 rounding of all GEMM inputs ----------------
// float4 segments: x 4194304 | Wq 262144 | Wk 262144 | Wv 262144 | Wt 131072 | Wo 262144
__global__ void round_all_kernel(const float* __restrict__ x,  float* __restrict__ xr,
                                 const float* __restrict__ Wq, float* __restrict__ WqR,
                                 const float* __restrict__ Wk, float* __restrict__ WkR,
                                 const float* __restrict__ Wv, float* __restrict__ WvR,
                                 const float* __restrict__ Wt, float* __restrict__ WtR,
                                 const float* __restrict__ Wo, float* __restrict__ WoR)
{
    long i = (long)blockIdx.x*256 + threadIdx.x;
    const float* src; float* dst; long off;
    if (i < 4194304)                      { src=x;  dst=xr;  off=i; }
    else if (i < 4194304+262144)          { src=Wq; dst=WqR; off=i-4194304; }
    else if (i < 4194304+2*262144)        { src=Wk; dst=WkR; off=i-4194304-262144; }
    else if (i < 4194304+3*262144)        { src=Wv; dst=WvR; off=i-4194304-2*262144; }
    else if (i < 4194304+3*262144+131072) { src=Wt; dst=WtR; off=i-4194304-3*262144; }
    else if (i < 4194304+4*262144+131072) { src=Wo; dst=WoR; off=i-4194304-3*262144-131072; }
    else return;
    float4 v = reinterpret_cast<const float4*>(src)[off];
    v.x = tf32r(v.x); v.y = tf32r(v.y); v.z = tf32r(v.z); v.w = tf32r(v.w);
    reinterpret_cast<float4*>(dst)[off] = v;
}

// ---------------- GEMM core ------------
__device__ __forceinline__ void gemm_body(const float* __restrict__ A, const float* __restrict__ W,
                                          const float* __restrict__ bias, float* __restrict__ C,
                                          int N, int K, int act, int m0, int n0, float* smem)
{
    const int tid = threadIdx.x, warp = tid>>5;
    const int tr = warp>>1, tcw = warp&1;
    const int lr = tid>>3, lc = (tid&7)*4;

    wmma::fragment<wmma::accumulator,16,16,8,float> acc[2][2];
    #pragma unroll
    for(int i=0;i<2;i++)
        #pragma unroll
        for(int j=0;j<2;j++) wmma::fill_fragment(acc[i][j], 0.f);

    const int KT = K/GBK;

    {
        float* As = smem;
        float* Ws = As + GBM*GAP;
        #pragma unroll
        for (int s=0;s<4;s++){
            int r = lr + s*32;
            cp16(&As[r*GAP+lc], &A[(size_t)(m0+r)*K + lc]);
        }
        #pragma unroll
        for (int s=0;s<2;s++){
            int r = lr + s*32;
            cp16(&Ws[r*GAP+lc], &W[(size_t)(n0+r)*K + lc]);
        }
        asm volatile("cp.async.commit_group;");
    }

    int buf = 0;
    for (int it=0; it<KT; ++it){
        if (it+1 < KT){
            float* As = smem + (buf^1)*GSTAGE;
            float* Ws = As + GBM*GAP;
            const int k0 = (it+1)*GBK;
            #pragma unroll
            for (int s=0;s<4;s++){
                int r = lr + s*32;
                cp16(&As[r*GAP+lc], &A[(size_t)(m0+r)*K + k0 + lc]);
            }
            #pragma unroll
            for (int s=0;s<2;s++){
                int r = lr + s*32;
                cp16(&Ws[r*GAP+lc], &W[(size_t)(n0+r)*K + k0 + lc]);
            }
            asm volatile("cp.async.commit_group;");
            asm volatile("cp.async.wait_group 1;");
        } else {
            asm volatile("cp.async.wait_group 0;");
        }
        __syncthreads();

        float* As = smem + buf*GSTAGE;
        float* Ws = As + GBM*GAP;
        #pragma unroll
        for (int kk=0; kk<GBK; kk+=8){
            wmma::fragment<wmma::matrix_a,16,16,8,wmma::precision::tf32,wmma::row_major> af[2];
            wmma::fragment<wmma::matrix_b,16,16,8,wmma::precision::tf32,wmma::col_major> bf[2];
            #pragma unroll
            for (int i=0;i<2;i++)
                wmma::load_matrix_sync(af[i], &As[(tr*32+i*16)*GAP + kk], GAP);
            #pragma unroll
            for (int j=0;j<2;j++)
                wmma::load_matrix_sync(bf[j], &Ws[(tcw*32+j*16)*GAP + kk], GAP);
            #pragma unroll
            for (int i=0;i<2;i++)
                #pragma unroll
                for (int j=0;j<2;j++)
                    wmma::mma_sync(acc[i][j], af[i], bf[j], acc[i][j]);
        }
        __syncthreads();
        buf ^= 1;
    }

    if (!bias && act == 0){
        #pragma unroll
        for (int i=0;i<2;i++)
            #pragma unroll
            for (int j=0;j<2;j++)
                wmma::store_matrix_sync(&C[(size_t)(m0+tr*32+i*16)*N + n0 + tcw*32 + j*16],
                                        acc[i][j], N, wmma::mem_row_major);
        return;
    }

    float* Cs = smem;
    #pragma unroll
    for (int i=0;i<2;i++)
        #pragma unroll
        for (int j=0;j<2;j++)
            wmma::store_matrix_sync(&Cs[(tr*32+i*16)*72 + tcw*32 + j*16], acc[i][j], 72, wmma::mem_row_major);
    __syncthreads();

    for (int idx = tid; idx < GBM*GBN/4; idx += 256){
        int row = idx >> 4, col = (idx & 15)*4;
        float4 v4 = *reinterpret_cast<float4*>(&Cs[row*72 + col]);
        float* vv = (float*)&v4;
        #pragma unroll
        for (int j=0;j<4;j++){
            float v = vv[j];
            if (bias) v += bias[n0+col+j];
            if (act==1) v = v/(1.f+expf(-v));
            vv[j] = v;
        }
        *reinterpret_cast<float4*>(&C[(size_t)(m0+row)*N + n0+col]) = v4;
    }
}

// ---------------- mega GEMM ----------
__global__ void __launch_bounds__(256, 4)
megagemm_kernel(const float* __restrict__ x,
                const float* __restrict__ Wq, const float* __restrict__ Wk,
                const float* __restrict__ Wv, const float* __restrict__ Wt,
                const float* __restrict__ bt,
                float* __restrict__ qpre, float* __restrict__ kpre,
                float* __restrict__ vpre, float* __restrict__ zb)
{
    extern __shared__ float smem[];
    const int bx = blockIdx.x;
    const int m0 = blockIdx.y*GBM;
    const float* W; float* C; const float* bias = nullptr;
    int N, act = 0, nb;
    if (bx < 16)      { W = Wq; C = qpre; N = 1024; nb = bx; }
    else if (bx < 32) { W = Wk; C = kpre; N = 1024; nb = bx-16; }
    else if (bx < 48) { W = Wv; C = vpre; N = 1024; nb = bx-32; }
    else              { W = Wt; C = zb;   N = 512;  nb = bx-48; bias = bt; act = 1; }
    gemm_body(x, W, bias, C, N, 1024, act, m0, nb*GBN, smem);
}

__global__ void __launch_bounds__(256, 4)
gemm_tf32_kernel(const float* __restrict__ A, const float* __restrict__ W,
                 float* __restrict__ C, int N, int K)
{
    extern __shared__ float smem[];
    gemm_body(A, W, nullptr, C, N, K, 0, blockIdx.y*GBM, blockIdx.x*GBN, smem);
}

// ---------------- beta/gs/gl ----------------
__global__ void smallproj_kernel(const float* __restrict__ x,
                                 const float* __restrict__ Wb, const float* __restrict__ Wds,
                                 const float* __restrict__ bds, const float* __restrict__ Wdl,
                                 const float* __restrict__ bdl,
                                 float* __restrict__ beta, float* __restrict__ gs,
                                 float* __restrict__ gl)
{
    extern __shared__ float Ws[];
    const int tid = threadIdx.x, lane = tid&31, warp = tid>>5;
    for (int idx = tid; idx < 12*256; idx += 256){
        int r = idx >> 8, c4 = (idx & 255)*4;
        const float* src = (r<4) ? Wb + r*1024 + c4 :
                           (r<8) ? Wds + (r-4)*1024 + c4 : Wdl + (r-8)*1024 + c4;
        *reinterpret_cast<float4*>(&Ws[r*1024 + c4]) = *reinterpret_cast<const float4*>(src);
    }
    __syncthreads();

    #pragma unroll
    for (int rr=0; rr<2; rr++){
        const int row = blockIdx.x*16 + warp*2 + rr;
        const float* xr = x + (size_t)row*Dq;
        float acc[12];
        #pragma unroll
        for (int r=0;r<12;r++) acc[r]=0.f;
        #pragma unroll
        for (int it=0; it<8; it++){
            const int j = it*128 + lane*4;
            float4 xv4 = *reinterpret_cast<const float4*>(xr + j);
            const float* xv = (const float*)&xv4;
            #pragma unroll
            for (int r=0;r<12;r++){
                float a = acc[r];
                a = fmaf(xv[0], Ws[r*1024+j],   a);
                a = fmaf(xv[1], Ws[r*1024+j+1], a);
                a = fmaf(xv[2], Ws[r*1024+j+2], a);
                a = fmaf(xv[3], Ws[r*1024+j+3], a);
                acc[r] = a;
            }
        }
        #pragma unroll
        for (int r=0;r<12;r++) acc[r] = warp_sum(acc[r]);

        if (lane < 12){
            const int h = lane & 3;
            const int b = row >> 12, l = row & (Lq-1);
            size_t o = (size_t)(b*4 + h)*Lq + l;
            if (lane < 4)      beta[o] = sigm(acc[h]);
            else if (lane < 8) gs[o]   = sigm(acc[4+h] + bds[h]);
            else               gl[o]   = sigm(acc[8+h] + bdl[h]);
        }
    }
}

// ---------------- chunk_pre: fused conv+silu + delta precompute (wmma) -------
__global__ void chunk_pre_kernel(const float* __restrict__ qpre, const float* __restrict__ kpre,
                                 const float* __restrict__ vpre,
                                 const float* __restrict__ cqw, const float* __restrict__ ckw,
                                 const float* __restrict__ cvw,
                                 float* __restrict__ q, float* __restrict__ k,
                                 float* __restrict__ vb, const float* __restrict__ beta,
                                 float* __restrict__ u, float* __restrict__ w,
                                 float* __restrict__ attn)
{
    extern __shared__ float sm[];
    float* qs  = sm;
    float* ks  = qs + 32*QLD;
    float* vs  = ks + 32*QLD;
    float* Hs  = vs + 32*QLD;
    float* att = Hs + 35*QLD;
    float* Lm  = att+ 32*36;
    float* Ti  = Lm + 32*36;
    float* bs  = Ti + 32*36;
    const int bh = blockIdx.x >> 7, c = blockIdx.x & 127;
    const int b = bh >> 2, h = bh & 3;
    const int l0 = c*CHK;
    const int tid = threadIdx.x, lane = tid&31, wid = tid>>5;
    const size_t base = (size_t)bh*Lq + (size_t)l0;

    if (tid < 32) bs[tid] = beta[base + tid];

    const int d4f = (tid & 63)*4;
    const int i0r = (tid >> 6)*8;
    #pragma unroll
    for (int t = 0; t < 3; t++){
        const float* P = (t==0) ? qpre : (t==1) ? kpre : vpre;
        const float* T = (t==0) ? cqw  : (t==1) ? ckw  : cvw;
        float* D = (t==0) ? qs : (t==1) ? ks : vs;

        for (int idx = tid; idx < 35*64; idx += 256){
            int jj = idx >> 6, d4 = (idx & 63)*4;
            int gl = l0 - 3 + jj;
            float4 val = make_float4(0.f,0.f,0.f,0.f);
            if (gl >= 0)
                val = *reinterpret_cast<const float4*>(P + (size_t)(b*Lq + gl)*Dq + h*256 + d4);
            *reinterpret_cast<float4*>(&Hs[jj*QLD + d4]) = val;
        }
        __syncthreads();

        float4 taps[4];
        #pragma unroll
        for (int c2=0;c2<4;c2++)
            taps[c2] = *reinterpret_cast<const float4*>(T + (h*256 + d4f + c2)*4);

        #pragma unroll
        for (int i = i0r; i < i0r+8; i++){
            float a[4] = {0.f,0.f,0.f,0.f};
            #pragma unroll
            for (int j=0;j<4;j++){
                float4 hv = *reinterpret_cast<float4*>(&Hs[(i+j)*QLD + d4f]);
                const float* hvf = (const float*)&hv;
                #pragma unroll
                for (int c2=0;c2<4;c2++)
                    a[c2] = fmaf(hvf[c2], ((const float*)&taps[c2])[j], a[c2]);
            }
            float4 o;
            float* of = (float*)&o;
            #pragma unroll
            for (int c2=0;c2<4;c2++) of[c2] = silu(a[c2]);
            *reinterpret_cast<float4*>(&D[i*QLD + d4f]) = o;
            if (t == 2)
                *reinterpret_cast<float4*>(&vb[(base+i)*256 + d4f]) = o;
        }
        __syncthreads();
    }

    #pragma unroll
    for (int r=0;r<4;r++){
        int i = wid*4 + r;
        float sq=0.f, sk=0.f;
        for (int d=lane; d<256; d+=32){
            float a=qs[i*QLD+d]; sq=fmaf(a,a,sq);
            float bb=ks[i*QLD+d]; sk=fmaf(bb,bb,sk);
        }
        sq = warp_sum(sq); sk = warp_sum(sk);
        float rq = rsqrtf(sq + 1e-6f), rk = rsqrtf(sk + 1e-6f);
        for (int d=lane; d<256; d+=32){
            qs[i*QLD+d] = tf32r(qs[i*QLD+d]*rq);
            ks[i*QLD+d] = tf32r(ks[i*QLD+d]*rk);
        }
    }
    __syncthreads();

    for (int idx = tid; idx < 32*64; idx += 256){
        int i = idx>>6, d4 = (idx&63)*4;
        size_t g = (base+i)*256 + d4;
        *reinterpret_cast<float4*>(&q[g]) = *reinterpret_cast<float4*>(&qs[i*QLD+d4]);
        *reinterpret_cast<float4*>(&k[g]) = *reinterpret_cast<float4*>(&ks[i*QLD+d4]);
        float bb = bs[i];
        float4 vv = *reinterpret_cast<float4*>(&vs[i*QLD+d4]);
        vv.x = tf32r(vv.x*bb); vv.y = tf32r(vv.y*bb); vv.z = tf32r(vv.z*bb); vv.w = tf32r(vv.w*bb);
        *reinterpret_cast<float4*>(&vs[i*QLD+d4]) = vv;
    }
    __syncthreads();

    {
        const int ww = wid & 3;
        const int j0 = (ww & 1)*16, i0 = (ww >> 1)*16;
        const float* Asrc = (wid < 4) ? qs : ks;
        float* dst = (wid < 4) ? att : Lm;
        wmma::fragment<wmma::accumulator,16,16,8,float> acc;
        wmma::fill_fragment(acc, 0.f);
        #pragma unroll 4
        for (int dk0 = 0; dk0 < 256; dk0 += 8){
            wmma::fragment<wmma::matrix_a,16,16,8,wmma::precision::tf32,wmma::row_major> af;
            wmma::load_matrix_sync(af, Asrc + i0*QLD + dk0, QLD);
            wmma::fragment<wmma::matrix_b,16,16,8,wmma::precision::tf32,wmma::col_major> bf;
            wmma::load_matrix_sync(bf, ks + j0*QLD + dk0, QLD);
            wmma::mma_sync(acc, af, bf, acc);
        }
        wmma::store_matrix_sync(dst + i0*36 + j0, acc, 36, wmma::mem_row_major);
    }
    __syncthreads();

    for (int idx = tid; idx < 1024; idx += 256){
        int i = idx>>5, j = idx&31;
        attn[(size_t)blockIdx.x*1024 + idx] = (j <= i) ? tf32r(att[i*36+j]) : 0.f;
        Lm[i*36+j] = (j < i) ? bs[i]*Lm[i*36+j] : 0.f;
    }
    __syncthreads();

    if (wid == 0){
        for (int i=0;i<32;i++){
            float xv = (lane==i) ? 1.f : 0.f;
            for (int p=0;p<i;p++) xv = fmaf(-Lm[i*36+p], Ti[p*36+lane], xv);
            Ti[i*36+lane] = xv;
            __syncwarp();
        }
    }
    __syncthreads();

    for (int idx = tid; idx < 1024; idx += 256){
        int i = idx>>5, j = idx&31;
        float t = Ti[i*36+j];
        Lm[i*36+j]  = tf32r(t);
        att[i*36+j] = -tf32r(t*bs[j]);
    }
    __syncthreads();

    #pragma unroll
    for (int t = 0; t < 8; t++){
        const int id = wid*8 + t;
        const bool isU = id < 32;
        const int tile = isU ? id : id - 32;
        const int i0 = (tile & 1)*16;
        const int j0 = (tile >> 1)*16;
        const float* A = isU ? Lm : att;
        const float* B = isU ? vs : ks;
        wmma::fragment<wmma::accumulator,16,16,8,float> acc;
        wmma::fill_fragment(acc, 0.f);
        #pragma unroll
        for (int m0 = 0; m0 < 32; m0 += 8){
            wmma::fragment<wmma::matrix_a,16,16,8,wmma::precision::tf32,wmma::row_major> af;
            wmma::load_matrix_sync(af, A + i0*36 + m0, 36);
            wmma::fragment<wmma::matrix_b,16,16,8,wmma::precision::tf32,wmma::row_major> bf;
            wmma::load_matrix_sync(bf, B + m0*QLD + j0, QLD);
            wmma::mma_sync(acc, af, bf, acc);
        }
        if (isU)
            wmma::store_matrix_sync(u + (base+i0)*256 + j0, acc, 256, wmma::mem_row_major);
        else
            wmma::store_matrix_sync(qs + i0*QLD + j0, acc, QLD, wmma::mem_row_major);
    }
    __syncthreads();

    for (int idx = tid; idx < 32*64; idx += 256){
        int i = idx>>6, d4 = (idx&63)*4;
        float4 vv = *reinterpret_cast<float4*>(&qs[i*QLD+d4]);
        vv.x = tf32r(vv.x); vv.y = tf32r(vv.y); vv.z = tf32r(vv.z); vv.w = tf32r(vv.w);
        *reinterpret_cast<float4*>(&w[(base+i)*256 + d4]) = vv;
    }
}

// ---------------- fused: delta-scan (0-127) + dual EMA (128-143) ----
// Phase-2 S-update spread over all 8 warps (4 tiles each).
__global__ void scan_ema_kernel(const float* __restrict__ q, const float* __restrict__ k,
                                const float* __restrict__ u, const float* __restrict__ w,
                                const float* __restrict__ attn, float* __restrict__ o,
                                const float* __restrict__ v, const float* __restrict__ gs,
                                const float* __restrict__ gl,
                                float* __restrict__ es, float* __restrict__ el)
{
    if (blockIdx.x >= 128){
        const int bh = blockIdx.x - 128;
        const int dv = threadIdx.x;
        const size_t vbase = (size_t)bh*Lq*256 + dv;
        const float* gsp = gs + (size_t)bh*Lq;
        const float* glp = gl + (size_t)bh*Lq;
        float ss = 0.f, sl = 0.f;
        #pragma unroll 8
        for (int t=0;t<Lq;t++){
            float vv = v[vbase + (size_t)t*256];
            float a = gsp[t], b2 = glp[t];
            ss = fmaf(a, ss, (1.f-a)*vv);
            sl = fmaf(b2, sl, (1.f-b2)*vv);
            es[vbase + (size_t)t*256] = ss;
            el[vbase + (size_t)t*256] = sl;
        }
        return;
    }

    extern __shared__ float sm[];
    float* S   = sm;
    float* Shi = S   + 256*SLD;
    float* Slo = Shi + 256*SLD;
    float* uhh = Slo + 256*SLD;
    float* uhl = uhh + 32*SLD;
    const int bh = blockIdx.x >> 3;
    const int d0 = (blockIdx.x & 7) * 32;
    const int tid = threadIdx.x, warp = tid >> 5;

    for (int i = tid; i < SCAN_SMEM_FLOATS; i += 256) sm[i] = 0.f;
    __syncthreads();

    wmma::fragment<wmma::accumulator,16,16,8,float> acc2;

    for (int c = 0; c < NCHK; ++c){
        const size_t base = (size_t)bh*Lq + (size_t)c*32;
        const float* qg = q + base*256;
        const float* kg = k + base*256;
        const float* wg = w + base*256;
        const float* ug = u + base*256 + d0;
        const float* ag = attn + ((size_t)bh*NCHK + c)*1024;
        float*       og = o + base*256 + d0;

        if (warp < 4){
            // uh = u + wneg @ (Shi + Slo); fragment-level split into uhh/uhl
            const int i0 = (warp & 1)*16, j0 = (warp >> 1)*16;
            wmma::fragment<wmma::accumulator,16,16,8,float> acc;
            wmma::load_matrix_sync(acc, ug + (size_t)i0*256 + j0, 256, wmma::mem_row_major);
            #pragma unroll 4
            for (int dk0 = 0; dk0 < 256; dk0 += 8){
                wmma::fragment<wmma::matrix_a,16,16,8,wmma::precision::tf32,wmma::row_major> af;
                wmma::load_matrix_sync(af, wg + (size_t)i0*256 + dk0, 256);
                wmma::fragment<wmma::matrix_b,16,16,8,wmma::precision::tf32,wmma::row_major> bf;
                wmma::load_matrix_sync(bf, Shi + dk0*SLD + j0, SLD);
                wmma::mma_sync(acc, af, bf, acc);
                wmma::load_matrix_sync(bf, Slo + dk0*SLD + j0, SLD);
                wmma::mma_sync(acc, af, bf, acc);
            }
            wmma::fragment<wmma::accumulator,16,16,8,float> ahi, alo;
            #pragma unroll
            for (int t=0;t<acc.num_elements;t++){
                float s = acc.x[t];
                float hi = __uint_as_float(__float_as_uint(s) & 0xFFFFE000u);
                ahi.x[t] = hi;
                alo.x[t] = tf32r(s - hi);
            }
            wmma::store_matrix_sync(uhh + i0*SLD + j0, ahi, SLD, wmma::mem_row_major);
            wmma::store_matrix_sync(uhl + i0*SLD + j0, alo, SLD, wmma::mem_row_major);
        } else {
            // q @ Shi (output path)
            const int i0 = ((warp-4) & 1)*16, j0 = ((warp-4) >> 1)*16;
            wmma::fill_fragment(acc2, 0.f);
            #pragma unroll 4
            for (int dk0 = 0; dk0 < 256; dk0 += 8){
                wmma::fragment<wmma::matrix_a,16,16,8,wmma::precision::tf32,wmma::row_major> af;
                wmma::load_matrix_sync(af, qg + (size_t)i0*256 + dk0, 256);
                wmma::fragment<wmma::matrix_b,16,16,8,wmma::precision::tf32,wmma::row_major> bf;
                wmma::load_matrix_sync(bf, Shi + dk0*SLD + j0, SLD);
                wmma::mma_sync(acc2, af, bf, acc2);
            }
        }
        __syncthreads();

        // warps 4-7: finish o first (reads uhh/uhl from phase 1; no S dependency)
        if (warp >= 4){
            const int i0 = ((warp-4) & 1)*16, j0 = ((warp-4) >> 1)*16;
            #pragma unroll
            for (int i2 = 0; i2 < 32; i2 += 8){
                wmma::fragment<wmma::matrix_a,16,16,8,wmma::precision::tf32,wmma::row_major> af;
                wmma::load_matrix_sync(af, ag + i0*32 + i2, 32);
                wmma::fragment<wmma::matrix_b,16,16,8,wmma::precision::tf32,wmma::row_major> bf;
                wmma::load_matrix_sync(bf, uhh + i2*SLD + j0, SLD);
                wmma::mma_sync(acc2, af, bf, acc2);
                wmma::load_matrix_sync(bf, uhl + i2*SLD + j0, SLD);
                wmma::mma_sync(acc2, af, bf, acc2);
            }
            wmma::store_matrix_sync(og + (size_t)i0*256 + j0, acc2, 256, wmma::mem_row_major);
        }

        // ALL warps: S += k^T @ (uhh + uhl); 4 tiles each (32 tiles total)
        #pragma unroll
        for (int t = 0; t < 4; t++){
            const int id = warp*4 + t;
            const int dk0 = (id >> 1)*16, j0 = (id & 1)*16;
            wmma::fragment<wmma::accumulator,16,16,8,float> acc;
            wmma::load_matrix_sync(acc, S + dk0*SLD + j0, SLD, wmma::mem_row_major);
            #pragma unroll
            for (int i2 = 0; i2 < 32; i2 += 8){
                wmma::fragment<wmma::matrix_a,16,16,8,wmma::precision::tf32,wmma::col_major> af;
                wmma::load_matrix_sync(af, kg + (size_t)i2*256 + dk0, 256);
                wmma::fragment<wmma::matrix_b,16,16,8,wmma::precision::tf32,wmma::row_major> bf;
                wmma::load_matrix_sync(bf, uhh + i2*SLD + j0, SLD);
                wmma::mma_sync(acc, af, bf, acc);
                wmma::load_matrix_sync(bf, uhl + i2*SLD + j0, SLD);
                wmma::mma_sync(acc, af, bf, acc);
            }
            wmma::store_matrix_sync(S + dk0*SLD + j0, acc, SLD, wmma::mem_row_major);
            wmma::fragment<wmma::accumulator,16,16,8,float> ahi, alo;
            #pragma unroll
            for (int tt=0;tt<acc.num_elements;tt++){
                float s = acc.x[tt];
                float hi = __uint_as_float(__float_as_uint(s) & 0xFFFFE000u);
                ahi.x[tt] = hi;
                alo.x[tt] = tf32r(s - hi);
            }
            wmma::store_matrix_sync(Shi + dk0*SLD + j0, ahi, SLD, wmma::mem_row_major);
            wmma::store_matrix_sync(Slo + dk0*SLD + j0, alo, SLD, wmma::mem_row_major);
        }
        __syncthreads();
    }
}

// ---------------- gate heads ----------------
__global__ void gate_head_kernel(const float* __restrict__ z,
                                 const float* __restrict__ Wc, const float* __restrict__ bc,
                                 const float* __restrict__ Wl, const float* __restrict__ bl,
                                 const float* __restrict__ Wg, const float* __restrict__ bg,
                                 const float* __restrict__ ltc, const float* __restrict__ ltf,
                                 float* __restrict__ wgt)
{
    extern __shared__ float Ws[];
    const int tid = threadIdx.x, lane = tid&31, warp = tid>>5;
    for (int idx = tid; idx < 24*128; idx += 256){
        int r = idx >> 7, c4 = (idx & 127)*4;
        const float* src = (r<8) ? Wc + r*512 + c4 :
                           (r<16)? Wl + (r-8)*512 + c4 : Wg + (r-16)*512 + c4;
        *reinterpret_cast<float4*>(&Ws[r*512 + c4]) = *reinterpret_cast<const float4*>(src);
    }
    __syncthreads();

    #pragma unroll
    for (int rr=0; rr<2; rr++){
        const int row = blockIdx.x*16 + warp*2 + rr;
        const float* zr = z + (size_t)row*512;
        float acc[24];
        #pragma unroll
        for (int r=0;r<24;r++) acc[r]=0.f;
        for (int j=lane; j<512; j+=32){
            float zv = zr[j];
            #pragma unroll
            for (int r=0;r<24;r++) acc[r] = fmaf(zv, Ws[r*512+j], acc[r]);
        }
        #pragma unroll
        for (int r=0;r<24;r++) acc[r] = warp_sum(acc[r]);

        if (lane < 4){
            const int h = lane;
            float tc = log1pf(expf(ltc[h])) + 1e-4f;
            float tf = log1pf(expf(ltf[h])) + 1e-4f;
            float c0 = acc[2*h]+bc[2*h],      c1 = acc[2*h+1]+bc[2*h+1];
            float l0 = acc[8+2*h]+bl[2*h],    l1 = acc[8+2*h+1]+bl[2*h+1];
            float g0 = acc[16+2*h]+bg[2*h],   g1 = acc[16+2*h+1]+bg[2*h+1];
            float pg0 = sigm((c0-c1)/tc), pg1 = 1.f - pg0;
            float q0  = sigm((l0-l1)/tf), q1 = 1.f - q0;
            float r0  = sigm((g0-g1)/tf), r1 = 1.f - r0;
            size_t o = (size_t)row*16 + h*4;
            wgt[o+0] = pg0*q0; wgt[o+1] = pg0*q1; wgt[o+2] = pg1*r0; wgt[o+3] = pg1*r1;
        }
    }
}

// ---------------- mix + per-head RMSNorm ----------------
__global__ void combine_kernel(const float* __restrict__ v, const float* __restrict__ es,
                               const float* __restrict__ el, const float* __restrict__ dl,
                               const float* __restrict__ wgt, const float* __restrict__ onw,
                               float* __restrict__ omix)
{
    const int gw = blockIdx.x*8 + (threadIdx.x>>5);
    const int row = gw >> 2, h = gw & 3;
    const int b = row >> 12, l = row & (Lq-1);
    const int lane = threadIdx.x & 31;
    const size_t gbase = ((size_t)(b*4+h)*Lq + l)*256;
    const float* wp = wgt + (size_t)row*16 + h*4;
    const float w0 = wp[0], w1 = wp[1], w2 = wp[2], w3 = wp[3];

    float4 vals[2];
    float ss = 0.f;
    #pragma unroll
    for (int s=0;s<2;s++){
        const int d = lane*4 + s*128;
        float4 a = *reinterpret_cast<const float4*>(v  + gbase + d);
        float4 b4= *reinterpret_cast<const float4*>(es + gbase + d);
        float4 c4= *reinterpret_cast<const float4*>(dl + gbase + d);
        float4 d4= *reinterpret_cast<const float4*>(el + gbase + d);
        float* av=(float*)&a; float* bv=(float*)&b4; float* cv=(float*)&c4; float* dv=(float*)&d4;
        float* ov=(float*)&vals[s];
        #pragma unroll
        for (int j=0;j<4;j++){
            float val = w0*av[j] + w1*bv[j] + w2*cv[j] + w3*dv[j];
            ov[j] = val;
            ss = fmaf(val, val, ss);
        }
    }
    ss = warp_sum(ss);
    const float rms = rsqrtf(ss*(1.f/256.f) + 1e-5f);
    float* op = omix + (size_t)row*1024 + h*256;
    #pragma unroll
    for (int s=0;s<2;s++){
        const int d = lane*4 + s*128;
        float4 w4 = *reinterpret_cast<const float4*>(onw + d);
        float* wv=(float*)&w4; float* ov=(float*)&vals[s];
        float4 r;
        float* rv=(float*)&r;
        #pragma unroll
        for (int j=0;j<4;j++) rv[j] = tf32r(ov[j]*rms*wv[j]);
        *reinterpret_cast<float4*>(op + d) = r;
    }
}

// ---------------- host ----------------
extern "C" void kernel_launch(void* const* d_in, const int* in_sizes, int n_in,
                              void* d_out, int out_size)
{
    const float* x      = (const float*)d_in[0];
    const float* Wq     = (const float*)d_in[1];
    const float* Wk     = (const float*)d_in[2];
    const float* Wv     = (const float*)d_in[3];
    const float* cqw    = (const float*)d_in[4];
    const float* ckw    = (const float*)d_in[5];
    const float* cvw    = (const float*)d_in[6];
    const float* Wb     = (const float*)d_in[7];
    const float* Wds    = (const float*)d_in[8];
    const float* bds    = (const float*)d_in[9];
    const float* Wdl    = (const float*)d_in[10];
    const float* bdl    = (const float*)d_in[11];
    const float* Wtrunk = (const float*)d_in[12];
    const float* btrunk = (const float*)d_in[13];
    const float* Wcoarse= (const float*)d_in[14];
    const float* bcoarse= (const float*)d_in[15];
    const float* Wlocal = (const float*)d_in[16];
    const float* blocal = (const float*)d_in[17];
    const float* Wglobal= (const float*)d_in[18];
    const float* bglobal= (const float*)d_in[19];
    const float* ltc    = (const float*)d_in[20];
    const float* ltf    = (const float*)d_in[21];
    const float* onw    = (const float*)d_in[22];
    const float* Wo     = (const float*)d_in[23];
    float* out = (float*)d_out;

    float* arena;
    cudaGetSymbolAddress((void**)&arena, g_arena);
    float* qpre = arena + OFF_QPRE;
    float* kpre = arena + OFF_KPRE;
    float* vpre = arena + OFF_VPRE;
    float* qb   = arena + OFF_Q;
    float* kb   = arena + OFF_K;
    float* vb   = arena + OFF_V;
    float* ub   = arena + OFF_UB;
    float* wb   = arena + OFF_WB;
    float* dlt  = arena + OFF_DELTA;
    float* emas = arena + OFF_EMAS;
    float* emal = arena + OFF_EMAL;
    float* omix = arena + OFF_OMIX;
    float* zb   = arena + OFF_Z;
    float* attn = arena + OFF_ATTN;
    float* beta = arena + OFF_BETA;
    float* gs   = arena + OFF_GS;
    float* gl   = arena + OFF_GL;
    float* wgt  = arena + OFF_WGT;
    float* xr   = arena + OFF_XR;
    float* WqR  = arena + OFF_WQR;
    float* WkR  = arena + OFF_WKR;
    float* WvR  = arena + OFF_WVR;
    float* WtR  = arena + OFF_WTR;
    float* WoR  = arena + OFF_WOR;

    cudaFuncSetAttribute(megagemm_kernel,  cudaFuncAttributeMaxDynamicSharedMemorySize, GEMM_SMEM_BYTES);
    cudaFuncSetAttribute(gemm_tf32_kernel, cudaFuncAttributeMaxDynamicSharedMemorySize, GEMM_SMEM_BYTES);
    cudaFuncSetAttribute(chunk_pre_kernel, cudaFuncAttributeMaxDynamicSharedMemorySize, PRE_SMEM_BYTES);
    cudaFuncSetAttribute(scan_ema_kernel,  cudaFuncAttributeMaxDynamicSharedMemorySize, SCAN_SMEM_BYTES);
    cudaFuncSetAttribute(gate_head_kernel, cudaFuncAttributeMaxDynamicSharedMemorySize, GATE_SMEM_BYTES);
    cudaFuncSetAttribute(smallproj_kernel, cudaFuncAttributeMaxDynamicSharedMemorySize, SP_SMEM_BYTES);

    dim3 blk(256);

    // 0: fused rounding of all GEMM inputs (5373952 float4s)
    round_all_kernel<<<20992, blk>>>(x, xr, Wq, WqR, Wk, WkR, Wv, WvR, Wtrunk, WtR, Wo, WoR);

    // 1: beta / decays
    smallproj_kernel<<<MROWS/16, blk, SP_SMEM_BYTES>>>(x, Wb, Wds, bds, Wdl, bdl, beta, gs, gl);

    // 2: fused Q/K/V/trunk projections
    megagemm_kernel<<<dim3(56, MROWS/GBM), blk, GEMM_SMEM_BYTES>>>(
        xr, WqR, WkR, WvR, WtR, btrunk, qpre, kpre, vpre, zb);

    // 3: fused conv+silu + delta precompute  (profiled slot)
    chunk_pre_kernel<<<2048, blk, PRE_SMEM_BYTES>>>(qpre, kpre, vpre, cqw, ckw, cvw,
                                                    qb, kb, vb, beta, ub, wb, attn);

    // 4: fused scan + EMA (rebalanced phase 2)
    scan_ema_kernel<<<144, blk, SCAN_SMEM_BYTES>>>(qb, kb, ub, wb, attn, dlt,
                                                   vb, gs, gl, emas, emal);

    // 5: gate heads
    gate_head_kernel<<<MROWS/16, blk, GATE_SMEM_BYTES>>>(zb, Wcoarse, bcoarse, Wlocal, blocal,
                                                         Wglobal, bglobal, ltc, ltf, wgt);

    // 6: combine + RMSNorm
    combine_kernel<<<MROWS/2, blk>>>(vb, emas, emal, dlt, wgt, onw, omix);

    // 7: output projection
    gemm_tf32_kernel<<<dim3(1024/GBN, MROWS/GBM), blk, GEMM_SMEM_BYTES>>>(omix, WoR, out, 1024, 1024);
}

// round 17
// speedup vs baseline: 1.0939x; 1.0366x over previous
#include <cuda_runtime.h>
#include <math.h>
#include <mma.h>

using namespace nvcuda;

#define Hq   4
#define Lq   4096
#define Dq   1024
#define CHK  32
#define NCHK 128
#define MROWS 16384

// ---------------- scratch arena ----------------
constexpr size_t SZf      = 16777216ull;
constexpr size_t OFF_QPRE = 0;
constexpr size_t OFF_KPRE = SZf;
constexpr size_t OFF_VPRE = 2*SZf;
constexpr size_t OFF_DELTA= 2*SZf;               // dlt written after vpre consumed
constexpr size_t OFF_Q    = 3*SZf;
constexpr size_t OFF_K    = 4*SZf;
constexpr size_t OFF_V    = 5*SZf;
constexpr size_t OFF_EMAS = 6*SZf;
constexpr size_t OFF_EMAL = 7*SZf;
constexpr size_t OFF_OMIX = 8*SZf;
constexpr size_t OFF_Z    = 9*SZf;
constexpr size_t OFF_ATTN = OFF_Z + 8388608ull;
constexpr size_t OFF_BETA = OFF_ATTN + 2097152ull;
constexpr size_t OFF_GS   = OFF_BETA + 65536ull;
constexpr size_t OFF_GL   = OFF_GS + 65536ull;
constexpr size_t OFF_WGT  = OFF_GL + 65536ull;
constexpr size_t OFF_XR   = OFF_WGT + 262144ull;
constexpr size_t OFF_WQR  = OFF_XR + SZf;
constexpr size_t OFF_WKR  = OFF_WQR + 1048576ull;
constexpr size_t OFF_WVR  = OFF_WKR + 1048576ull;
constexpr size_t OFF_WTR  = OFF_WVR + 1048576ull;
constexpr size_t OFF_WOR  = OFF_WTR + 524288ull;
constexpr size_t OFF_UB   = OFF_WOR + 1048576ull;   // dedicated u (NO aliasing with qpre)
constexpr size_t OFF_WB   = OFF_UB + SZf;           // dedicated w (NO aliasing with kpre)
constexpr size_t ARENA_TOTAL = OFF_WB + SZf;

__device__ float g_arena[ARENA_TOTAL];

// chunk_pre smem: qs,ks,vs (32x264) + att,Lm,Ti (32x36) + bs  (NO halo buffer)
constexpr int QLD = 264;
constexpr int PRE_SMEM_FLOATS = 3*32*QLD + 3*32*36 + 32;   // 28832
constexpr int PRE_SMEM_BYTES  = PRE_SMEM_FLOATS*4;         // 115328 -> 2 blocks/SM

// scan smem
constexpr int SLD = 36;
constexpr int SCAN_SMEM_FLOATS = 3*256*SLD + 2*32*SLD;
constexpr int SCAN_SMEM_BYTES  = SCAN_SMEM_FLOATS * 4;    // 119808

// GEMM tiling
constexpr int GBM = 128, GBN = 64, GBK = 32, GAP = 36;
constexpr int GSTAGE = (GBM+GBN)*GAP;
constexpr int GEMM_SMEM_BYTES = 2*GSTAGE*4;

constexpr int GATE_SMEM_BYTES = 24*512*4;
constexpr int SP_SMEM_BYTES   = 12*1024*4;

__device__ __forceinline__ float sigm(float x){ return 1.f/(1.f+expf(-x)); }
__device__ __forceinline__ float silu(float x){ return x/(1.f+expf(-x)); }
__device__ __forceinline__ float tf32r(float x){ return wmma::__float_to_tf32(x); }

__device__ __forceinline__ float warp_sum(float v){
    #pragma unroll
    for (int o=16;o>0;o>>=1) v += __shfl_xor_sync(0xffffffffu, v, o);
    return v;
}

__device__ __forceinline__ void cp16(float* s, const float* g){
    unsigned a = (unsigned)__cvta_generic_to_shared(s);
    asm volatile("cp.async.cg.shared.global [%0], [%1], 16;" :: "r"(a), "l"(g));
}

// ---------------- fused tf32 rounding of all GEMM inputs ----------------
__global__ void round_all_kernel(const float* __restrict__ x,  float* __restrict__ xr,
                                 const float* __restrict__ Wq, float* __restrict__ WqR,
                                 const float* __restrict__ Wk, float* __restrict__ WkR,
                                 const float* __restrict__ Wv, float* __restrict__ WvR,
                                 const float* __restrict__ Wt, float* __restrict__ WtR,
                                 const float* __restrict__ Wo, float* __restrict__ WoR)
{
    long i = (long)blockIdx.x*256 + threadIdx.x;
    const float* src; float* dst; long off;
    if (i < 4194304)                      { src=x;  dst=xr;  off=i; }
    else if (i < 4194304+262144)          { src=Wq; dst=WqR; off=i-4194304; }
    else if (i < 4194304+2*262144)        { src=Wk; dst=WkR; off=i-4194304-262144; }
    else if (i < 4194304+3*262144)        { src=Wv; dst=WvR; off=i-4194304-2*262144; }
    else if (i < 4194304+3*262144+131072) { src=Wt; dst=WtR; off=i-4194304-3*262144; }
    else if (i < 4194304+4*262144+131072) { src=Wo; dst=WoR; off=i-4194304-3*262144-131072; }
    else return;
    float4 v = reinterpret_cast<const float4*>(src)[off];
    v.x = tf32r(v.x); v.y = tf32r(v.y); v.z = tf32r(v.z); v.w = tf32r(v.w);
    reinterpret_cast<float4*>(dst)[off] = v;
}

// ---------------- GEMM core ------------
__device__ __forceinline__ void gemm_body(const float* __restrict__ A, const float* __restrict__ W,
                                          const float* __restrict__ bias, float* __restrict__ C,
                                          int N, int K, int act, int m0, int n0, float* smem)
{
    const int tid = threadIdx.x, warp = tid>>5;
    const int tr = warp>>1, tcw = warp&1;
    const int lr = tid>>3, lc = (tid&7)*4;

    wmma::fragment<wmma::accumulator,16,16,8,float> acc[2][2];
    #pragma unroll
    for(int i=0;i<2;i++)
        #pragma unroll
        for(int j=0;j<2;j++) wmma::fill_fragment(acc[i][j], 0.f);

    const int KT = K/GBK;

    {
        float* As = smem;
        float* Ws = As + GBM*GAP;
        #pragma unroll
        for (int s=0;s<4;s++){
            int r = lr + s*32;
            cp16(&As[r*GAP+lc], &A[(size_t)(m0+r)*K + lc]);
        }
        #pragma unroll
        for (int s=0;s<2;s++){
            int r = lr + s*32;
            cp16(&Ws[r*GAP+lc], &W[(size_t)(n0+r)*K + lc]);
        }
        asm volatile("cp.async.commit_group;");
    }

    int buf = 0;
    for (int it=0; it<KT; ++it){
        if (it+1 < KT){
            float* As = smem + (buf^1)*GSTAGE;
            float* Ws = As + GBM*GAP;
            const int k0 = (it+1)*GBK;
            #pragma unroll
            for (int s=0;s<4;s++){
                int r = lr + s*32;
                cp16(&As[r*GAP+lc], &A[(size_t)(m0+r)*K + k0 + lc]);
            }
            #pragma unroll
            for (int s=0;s<2;s++){
                int r = lr + s*32;
                cp16(&Ws[r*GAP+lc], &W[(size_t)(n0+r)*K + k0 + lc]);
            }
            asm volatile("cp.async.commit_group;");
            asm volatile("cp.async.wait_group 1;");
        } else {
            asm volatile("cp.async.wait_group 0;");
        }
        __syncthreads();

        float* As = smem + buf*GSTAGE;
        float* Ws = As + GBM*GAP;
        #pragma unroll
        for (int kk=0; kk<GBK; kk+=8){
            wmma::fragment<wmma::matrix_a,16,16,8,wmma::precision::tf32,wmma::row_major> af[2];
            wmma::fragment<wmma::matrix_b,16,16,8,wmma::precision::tf32,wmma::col_major> bf[2];
            #pragma unroll
            for (int i=0;i<2;i++)
                wmma::load_matrix_sync(af[i], &As[(tr*32+i*16)*GAP + kk], GAP);
            #pragma unroll
            for (int j=0;j<2;j++)
                wmma::load_matrix_sync(bf[j], &Ws[(tcw*32+j*16)*GAP + kk], GAP);
            #pragma unroll
            for (int i=0;i<2;i++)
                #pragma unroll
                for (int j=0;j<2;j++)
                    wmma::mma_sync(acc[i][j], af[i], bf[j], acc[i][j]);
        }
        __syncthreads();
        buf ^= 1;
    }

    if (!bias && act == 0){
        #pragma unroll
        for (int i=0;i<2;i++)
            #pragma unroll
            for (int j=0;j<2;j++)
                wmma::store_matrix_sync(&C[(size_t)(m0+tr*32+i*16)*N + n0 + tcw*32 + j*16],
                                        acc[i][j], N, wmma::mem_row_major);
        return;
    }

    float* Cs = smem;
    #pragma unroll
    for (int i=0;i<2;i++)
        #pragma unroll
        for (int j=0;j<2;j++)
            wmma::store_matrix_sync(&Cs[(tr*32+i*16)*72 + tcw*32 + j*16], acc[i][j], 72, wmma::mem_row_major);
    __syncthreads();

    for (int idx = tid; idx < GBM*GBN/4; idx += 256){
        int row = idx >> 4, col = (idx & 15)*4;
        float4 v4 = *reinterpret_cast<float4*>(&Cs[row*72 + col]);
        float* vv = (float*)&v4;
        #pragma unroll
        for (int j=0;j<4;j++){
            float v = vv[j];
            if (bias) v += bias[n0+col+j];
            if (act==1) v = v/(1.f+expf(-v));
            vv[j] = v;
        }
        *reinterpret_cast<float4*>(&C[(size_t)(m0+row)*N + n0+col]) = v4;
    }
}

// ---------------- mega GEMM ----------
__global__ void __launch_bounds__(256, 4)
megagemm_kernel(const float* __restrict__ x,
                const float* __restrict__ Wq, const float* __restrict__ Wk,
                const float* __restrict__ Wv, const float* __restrict__ Wt,
                const float* __restrict__ bt,
                float* __restrict__ qpre, float* __restrict__ kpre,
                float* __restrict__ vpre, float* __restrict__ zb)
{
    extern __shared__ float smem[];
    const int bx = blockIdx.x;
    const int m0 = blockIdx.y*GBM;
    const float* W; float* C; const float* bias = nullptr;
    int N, act = 0, nb;
    if (bx < 16)      { W = Wq; C = qpre; N = 1024; nb = bx; }
    else if (bx < 32) { W = Wk; C = kpre; N = 1024; nb = bx-16; }
    else if (bx < 48) { W = Wv; C = vpre; N = 1024; nb = bx-32; }
    else              { W = Wt; C = zb;   N = 512;  nb = bx-48; bias = bt; act = 1; }
    gemm_body(x, W, bias, C, N, 1024, act, m0, nb*GBN, smem);
}

__global__ void __launch_bounds__(256, 4)
gemm_tf32_kernel(const float* __restrict__ A, const float* __restrict__ W,
                 float* __restrict__ C, int N, int K)
{
    extern __shared__ float smem[];
    gemm_body(A, W, nullptr, C, N, K, 0, blockIdx.y*GBM, blockIdx.x*GBN, smem);
}

// ---------------- beta/gs/gl ----------------
__global__ void smallproj_kernel(const float* __restrict__ x,
                                 const float* __restrict__ Wb, const float* __restrict__ Wds,
                                 const float* __restrict__ bds, const float* __restrict__ Wdl,
                                 const float* __restrict__ bdl,
                                 float* __restrict__ beta, float* __restrict__ gs,
                                 float* __restrict__ gl)
{
    extern __shared__ float Ws[];
    const int tid = threadIdx.x, lane = tid&31, warp = tid>>5;
    for (int idx = tid; idx < 12*256; idx += 256){
        int r = idx >> 8, c4 = (idx & 255)*4;
        const float* src = (r<4) ? Wb + r*1024 + c4 :
                           (r<8) ? Wds + (r-4)*1024 + c4 : Wdl + (r-8)*1024 + c4;
        *reinterpret_cast<float4*>(&Ws[r*1024 + c4]) = *reinterpret_cast<const float4*>(src);
    }
    __syncthreads();

    #pragma unroll
    for (int rr=0; rr<2; rr++){
        const int row = blockIdx.x*16 + warp*2 + rr;
        const float* xr = x + (size_t)row*Dq;
        float acc[12];
        #pragma unroll
        for (int r=0;r<12;r++) acc[r]=0.f;
        #pragma unroll
        for (int it=0; it<8; it++){
            const int j = it*128 + lane*4;
            float4 xv4 = *reinterpret_cast<const float4*>(xr + j);
            const float* xv = (const float*)&xv4;
            #pragma unroll
            for (int r=0;r<12;r++){
                float a = acc[r];
                a = fmaf(xv[0], Ws[r*1024+j],   a);
                a = fmaf(xv[1], Ws[r*1024+j+1], a);
                a = fmaf(xv[2], Ws[r*1024+j+2], a);
                a = fmaf(xv[3], Ws[r*1024+j+3], a);
                acc[r] = a;
            }
        }
        #pragma unroll
        for (int r=0;r<12;r++) acc[r] = warp_sum(acc[r]);

        if (lane < 12){
            const int h = lane & 3;
            const int b = row >> 12, l = row & (Lq-1);
            size_t o = (size_t)(b*4 + h)*Lq + l;
            if (lane < 4)      beta[o] = sigm(acc[h]);
            else if (lane < 8) gs[o]   = sigm(acc[4+h] + bds[h]);
            else               gl[o]   = sigm(acc[8+h] + bdl[h]);
        }
    }
}

// ---------------- chunk_pre: fused conv+silu (register window) + delta precompute ----
__global__ void __launch_bounds__(256, 2)
chunk_pre_kernel(const float* __restrict__ qpre, const float* __restrict__ kpre,
                 const float* __restrict__ vpre,
                 const float* __restrict__ cqw, const float* __restrict__ ckw,
                 const float* __restrict__ cvw,
                 float* __restrict__ q, float* __restrict__ k,
                 float* __restrict__ vb, const float* __restrict__ beta,
                 float* __restrict__ u, float* __restrict__ w,
                 float* __restrict__ attn)
{
    extern __shared__ float sm[];
    float* qs  = sm;                  // 32*264
    float* ks  = qs + 32*QLD;
    float* vs  = ks + 32*QLD;
    float* att = vs + 32*QLD;         // 32*36
    float* Lm  = att+ 32*36;
    float* Ti  = Lm + 32*36;
    float* bs  = Ti + 32*36;
    const int bh = blockIdx.x >> 7, c = blockIdx.x & 127;
    const int b = bh >> 2, h = bh & 3;
    const int l0 = c*CHK;
    const int tid = threadIdx.x, lane = tid&31, wid = tid>>5;
    const size_t base = (size_t)bh*Lq + (size_t)l0;

    if (tid < 32) bs[tid] = beta[base + tid];

    // ---- conv + silu via register sliding window (no smem halo) ----
    const int d4f = (tid & 63)*4;     // 4-col slice
    const int i0r = (tid >> 6)*8;     // 8 output rows
    const size_t gcol = (size_t)(b*Lq)*Dq + h*256 + d4f;
    #pragma unroll
    for (int t = 0; t < 3; t++){
        const float* P = (t==0) ? qpre : (t==1) ? kpre : vpre;
        const float* T = (t==0) ? cqw  : (t==1) ? ckw  : cvw;
        float* D = (t==0) ? qs : (t==1) ? ks : vs;

        float4 taps[4];
        #pragma unroll
        for (int c2=0;c2<4;c2++)
            taps[c2] = *reinterpret_cast<const float4*>(T + (h*256 + d4f + c2)*4);

        float4 win[4];  // rows i-3 .. i
        #pragma unroll
        for (int j=0;j<3;j++){
            int gl = l0 + i0r - 3 + j;
            win[j] = (gl >= 0) ? *reinterpret_cast<const float4*>(P + gcol + (size_t)gl*Dq)
                               : make_float4(0.f,0.f,0.f,0.f);
        }
        #pragma unroll
        for (int i=0;i<8;i++){
            const int gl = l0 + i0r + i;
            win[3] = *reinterpret_cast<const float4*>(P + gcol + (size_t)gl*Dq);
            float a[4] = {0.f,0.f,0.f,0.f};
            #pragma unroll
            for (int j=0;j<4;j++){
                const float* hv = (const float*)&win[j];
                #pragma unroll
                for (int c2=0;c2<4;c2++)
                    a[c2] = fmaf(hv[c2], ((const float*)&taps[c2])[j], a[c2]);
            }
            float4 o;
            float* of = (float*)&o;
            #pragma unroll
            for (int c2=0;c2<4;c2++) of[c2] = silu(a[c2]);
            *reinterpret_cast<float4*>(&D[(i0r+i)*QLD + d4f]) = o;
            if (t == 2)
                *reinterpret_cast<float4*>(&vb[(base+i0r+i)*256 + d4f]) = o;
            win[0]=win[1]; win[1]=win[2]; win[2]=win[3];
        }
    }
    __syncthreads();

    // ---- l2norm rows -> round to tf32 in smem ----
    #pragma unroll
    for (int r=0;r<4;r++){
        int i = wid*4 + r;
        float sq=0.f, sk=0.f;
        for (int d=lane; d<256; d+=32){
            float a=qs[i*QLD+d]; sq=fmaf(a,a,sq);
            float bb=ks[i*QLD+d]; sk=fmaf(bb,bb,sk);
        }
        sq = warp_sum(sq); sk = warp_sum(sk);
        float rq = rsqrtf(sq + 1e-6f), rk = rsqrtf(sk + 1e-6f);
        for (int d=lane; d<256; d+=32){
            qs[i*QLD+d] = tf32r(qs[i*QLD+d]*rq);
            ks[i*QLD+d] = tf32r(ks[i*QLD+d]*rk);
        }
    }
    __syncthreads();

    for (int idx = tid; idx < 32*64; idx += 256){
        int i = idx>>6, d4 = (idx&63)*4;
        size_t g = (base+i)*256 + d4;
        *reinterpret_cast<float4*>(&q[g]) = *reinterpret_cast<float4*>(&qs[i*QLD+d4]);
        *reinterpret_cast<float4*>(&k[g]) = *reinterpret_cast<float4*>(&ks[i*QLD+d4]);
        float bb = bs[i];
        float4 vv = *reinterpret_cast<float4*>(&vs[i*QLD+d4]);
        vv.x = tf32r(vv.x*bb); vv.y = tf32r(vv.y*bb); vv.z = tf32r(vv.z*bb); vv.w = tf32r(vv.w*bb);
        *reinterpret_cast<float4*>(&vs[i*QLD+d4]) = vv;
    }
    __syncthreads();

    {
        const int ww = wid & 3;
        const int j0 = (ww & 1)*16, i0 = (ww >> 1)*16;
        const float* Asrc = (wid < 4) ? qs : ks;
        float* dst = (wid < 4) ? att : Lm;
        wmma::fragment<wmma::accumulator,16,16,8,float> acc;
        wmma::fill_fragment(acc, 0.f);
        #pragma unroll 4
        for (int dk0 = 0; dk0 < 256; dk0 += 8){
            wmma::fragment<wmma::matrix_a,16,16,8,wmma::precision::tf32,wmma::row_major> af;
            wmma::load_matrix_sync(af, Asrc + i0*QLD + dk0, QLD);
            wmma::fragment<wmma::matrix_b,16,16,8,wmma::precision::tf32,wmma::col_major> bf;
            wmma::load_matrix_sync(bf, ks + j0*QLD + dk0, QLD);
            wmma::mma_sync(acc, af, bf, acc);
        }
        wmma::store_matrix_sync(dst + i0*36 + j0, acc, 36, wmma::mem_row_major);
    }
    __syncthreads();

    for (int idx = tid; idx < 1024; idx += 256){
        int i = idx>>5, j = idx&31;
        attn[(size_t)blockIdx.x*1024 + idx] = (j <= i) ? tf32r(att[i*36+j]) : 0.f;
        Lm[i*36+j] = (j < i) ? bs[i]*Lm[i*36+j] : 0.f;
    }
    __syncthreads();

    if (wid == 0){
        for (int i=0;i<32;i++){
            float xv = (lane==i) ? 1.f : 0.f;
            for (int p=0;p<i;p++) xv = fmaf(-Lm[i*36+p], Ti[p*36+lane], xv);
            Ti[i*36+lane] = xv;
            __syncwarp();
        }
    }
    __syncthreads();

    for (int idx = tid; idx < 1024; idx += 256){
        int i = idx>>5, j = idx&31;
        float t = Ti[i*36+j];
        Lm[i*36+j]  = tf32r(t);
        att[i*36+j] = -tf32r(t*bs[j]);
    }
    __syncthreads();

    #pragma unroll
    for (int t = 0; t < 8; t++){
        const int id = wid*8 + t;
        const bool isU = id < 32;
        const int tile = isU ? id : id - 32;
        const int i0 = (tile & 1)*16;
        const int j0 = (tile >> 1)*16;
        const float* A = isU ? Lm : att;
        const float* B = isU ? vs : ks;
        wmma::fragment<wmma::accumulator,16,16,8,float> acc;
        wmma::fill_fragment(acc, 0.f);
        #pragma unroll
        for (int m0 = 0; m0 < 32; m0 += 8){
            wmma::fragment<wmma::matrix_a,16,16,8,wmma::precision::tf32,wmma::row_major> af;
            wmma::load_matrix_sync(af, A + i0*36 + m0, 36);
            wmma::fragment<wmma::matrix_b,16,16,8,wmma::precision::tf32,wmma::row_major> bf;
            wmma::load_matrix_sync(bf, B + m0*QLD + j0, QLD);
            wmma::mma_sync(acc, af, bf, acc);
        }
        if (isU)
            wmma::store_matrix_sync(u + (base+i0)*256 + j0, acc, 256, wmma::mem_row_major);
        else
            wmma::store_matrix_sync(qs + i0*QLD + j0, acc, QLD, wmma::mem_row_major);
    }
    __syncthreads();

    for (int idx = tid; idx < 32*64; idx += 256){
        int i = idx>>6, d4 = (idx&63)*4;
        float4 vv = *reinterpret_cast<float4*>(&qs[i*QLD+d4]);
        vv.x = tf32r(vv.x); vv.y = tf32r(vv.y); vv.z = tf32r(vv.z); vv.w = tf32r(vv.w);
        *reinterpret_cast<float4*>(&w[(base+i)*256 + d4]) = vv;
    }
}

// ---------------- fused: delta-scan (0-127) + dual EMA (128-143) ----
__global__ void scan_ema_kernel(const float* __restrict__ q, const float* __restrict__ k,
                                const float* __restrict__ u, const float* __restrict__ w,
                                const float* __restrict__ attn, float* __restrict__ o,
                                const float* __restrict__ v, const float* __restrict__ gs,
                                const float* __restrict__ gl,
                                float* __restrict__ es, float* __restrict__ el)
{
    if (blockIdx.x >= 128){
        const int bh = blockIdx.x - 128;
        const int dv = threadIdx.x;
        const size_t vbase = (size_t)bh*Lq*256 + dv;
        const float* gsp = gs + (size_t)bh*Lq;
        const float* glp = gl + (size_t)bh*Lq;
        float ss = 0.f, sl = 0.f;
        #pragma unroll 8
        for (int t=0;t<Lq;t++){
            float vv = v[vbase + (size_t)t*256];
            float a = gsp[t], b2 = glp[t];
            ss = fmaf(a, ss, (1.f-a)*vv);
            sl = fmaf(b2, sl, (1.f-b2)*vv);
            es[vbase + (size_t)t*256] = ss;
            el[vbase + (size_t)t*256] = sl;
        }
        return;
    }

    extern __shared__ float sm[];
    float* S   = sm;
    float* Shi = S   + 256*SLD;
    float* Slo = Shi + 256*SLD;
    float* uhh = Slo + 256*SLD;
    float* uhl = uhh + 32*SLD;
    const int bh = blockIdx.x >> 3;
    const int d0 = (blockIdx.x & 7) * 32;
    const int tid = threadIdx.x, warp = tid >> 5;

    for (int i = tid; i < SCAN_SMEM_FLOATS; i += 256) sm[i] = 0.f;
    __syncthreads();

    wmma::fragment<wmma::accumulator,16,16,8,float> acc2;

    for (int c = 0; c < NCHK; ++c){
        const size_t base = (size_t)bh*Lq + (size_t)c*32;
        const float* qg = q + base*256;
        const float* kg = k + base*256;
        const float* wg = w + base*256;
        const float* ug = u + base*256 + d0;
        const float* ag = attn + ((size_t)bh*NCHK + c)*1024;
        float*       og = o + base*256 + d0;

        if (warp < 4){
            const int i0 = (warp & 1)*16, j0 = (warp >> 1)*16;
            wmma::fragment<wmma::accumulator,16,16,8,float> acc;
            wmma::load_matrix_sync(acc, ug + (size_t)i0*256 + j0, 256, wmma::mem_row_major);
            #pragma unroll 4
            for (int dk0 = 0; dk0 < 256; dk0 += 8){
                wmma::fragment<wmma::matrix_a,16,16,8,wmma::precision::tf32,wmma::row_major> af;
                wmma::load_matrix_sync(af, wg + (size_t)i0*256 + dk0, 256);
                wmma::fragment<wmma::matrix_b,16,16,8,wmma::precision::tf32,wmma::row_major> bf;
                wmma::load_matrix_sync(bf, Shi + dk0*SLD + j0, SLD);
                wmma::mma_sync(acc, af, bf, acc);
                wmma::load_matrix_sync(bf, Slo + dk0*SLD + j0, SLD);
                wmma::mma_sync(acc, af, bf, acc);
            }
            wmma::fragment<wmma::accumulator,16,16,8,float> ahi, alo;
            #pragma unroll
            for (int t=0;t<acc.num_elements;t++){
                float s = acc.x[t];
                float hi = __uint_as_float(__float_as_uint(s) & 0xFFFFE000u);
                ahi.x[t] = hi;
                alo.x[t] = tf32r(s - hi);
            }
            wmma::store_matrix_sync(uhh + i0*SLD + j0, ahi, SLD, wmma::mem_row_major);
            wmma::store_matrix_sync(uhl + i0*SLD + j0, alo, SLD, wmma::mem_row_major);
        } else {
            const int i0 = ((warp-4) & 1)*16, j0 = ((warp-4) >> 1)*16;
            wmma::fill_fragment(acc2, 0.f);
            #pragma unroll 4
            for (int dk0 = 0; dk0 < 256; dk0 += 8){
                wmma::fragment<wmma::matrix_a,16,16,8,wmma::precision::tf32,wmma::row_major> af;
                wmma::load_matrix_sync(af, qg + (size_t)i0*256 + dk0, 256);
                wmma::fragment<wmma::matrix_b,16,16,8,wmma::precision::tf32,wmma::row_major> bf;
                wmma::load_matrix_sync(bf, Shi + dk0*SLD + j0, SLD);
                wmma::mma_sync(acc2, af, bf, acc2);
            }
        }
        __syncthreads();

        if (warp >= 4){
            const int i0 = ((warp-4) & 1)*16, j0 = ((warp-4) >> 1)*16;
            #pragma unroll
            for (int i2 = 0; i2 < 32; i2 += 8){
                wmma::fragment<wmma::matrix_a,16,16,8,wmma::precision::tf32,wmma::row_major> af;
                wmma::load_matrix_sync(af, ag + i0*32 + i2, 32);
                wmma::fragment<wmma::matrix_b,16,16,8,wmma::precision::tf32,wmma::row_major> bf;
                wmma::load_matrix_sync(bf, uhh + i2*SLD + j0, SLD);
                wmma::mma_sync(acc2, af, bf, acc2);
                wmma::load_matrix_sync(bf, uhl + i2*SLD + j0, SLD);
                wmma::mma_sync(acc2, af, bf, acc2);
            }
            wmma::store_matrix_sync(og + (size_t)i0*256 + j0, acc2, 256, wmma::mem_row_major);
        }

        #pragma unroll
        for (int t = 0; t < 4; t++){
            const int id = warp*4 + t;
            const int dk0 = (id >> 1)*16, j0 = (id & 1)*16;
            wmma::fragment<wmma::accumulator,16,16,8,float> acc;
            wmma::load_matrix_sync(acc, S + dk0*SLD + j0, SLD, wmma::mem_row_major);
            #pragma unroll
            for (int i2 = 0; i2 < 32; i2 += 8){
                wmma::fragment<wmma::matrix_a,16,16,8,wmma::precision::tf32,wmma::col_major> af;
                wmma::load_matrix_sync(af, kg + (size_t)i2*256 + dk0, 256);
                wmma::fragment<wmma::matrix_b,16,16,8,wmma::precision::tf32,wmma::row_major> bf;
                wmma::load_matrix_sync(bf, uhh + i2*SLD + j0, SLD);
                wmma::mma_sync(acc, af, bf, acc);
                wmma::load_matrix_sync(bf, uhl + i2*SLD + j0, SLD);
                wmma::mma_sync(acc, af, bf, acc);
            }
            wmma::store_matrix_sync(S + dk0*SLD + j0, acc, SLD, wmma::mem_row_major);
            wmma::fragment<wmma::accumulator,16,16,8,float> ahi, alo;
            #pragma unroll
            for (int tt=0;tt<acc.num_elements;tt++){
                float s = acc.x[tt];
                float hi = __uint_as_float(__float_as_uint(s) & 0xFFFFE000u);
                ahi.x[tt] = hi;
                alo.x[tt] = tf32r(s - hi);
            }
            wmma::store_matrix_sync(Shi + dk0*SLD + j0, ahi, SLD, wmma::mem_row_major);
            wmma::store_matrix_sync(Slo + dk0*SLD + j0, alo, SLD, wmma::mem_row_major);
        }
        __syncthreads();
    }
}

// ---------------- gate heads ----------------
__global__ void gate_head_kernel(const float* __restrict__ z,
                                 const float* __restrict__ Wc, const float* __restrict__ bc,
                                 const float* __restrict__ Wl, const float* __restrict__ bl,
                                 const float* __restrict__ Wg, const float* __restrict__ bg,
                                 const float* __restrict__ ltc, const float* __restrict__ ltf,
                                 float* __restrict__ wgt)
{
    extern __shared__ float Ws[];
    const int tid = threadIdx.x, lane = tid&31, warp = tid>>5;
    for (int idx = tid; idx < 24*128; idx += 256){
        int r = idx >> 7, c4 = (idx & 127)*4;
        const float* src = (r<8) ? Wc + r*512 + c4 :
                           (r<16)? Wl + (r-8)*512 + c4 : Wg + (r-16)*512 + c4;
        *reinterpret_cast<float4*>(&Ws[r*512 + c4]) = *reinterpret_cast<const float4*>(src);
    }
    __syncthreads();

    #pragma unroll
    for (int rr=0; rr<2; rr++){
        const int row = blockIdx.x*16 + warp*2 + rr;
        const float* zr = z + (size_t)row*512;
        float acc[24];
        #pragma unroll
        for (int r=0;r<24;r++) acc[r]=0.f;
        for (int j=lane; j<512; j+=32){
            float zv = zr[j];
            #pragma unroll
            for (int r=0;r<24;r++) acc[r] = fmaf(zv, Ws[r*512+j], acc[r]);
        }
        #pragma unroll
        for (int r=0;r<24;r++) acc[r] = warp_sum(acc[r]);

        if (lane < 4){
            const int h = lane;
            float tc = log1pf(expf(ltc[h])) + 1e-4f;
            float tf = log1pf(expf(ltf[h])) + 1e-4f;
            float c0 = acc[2*h]+bc[2*h],      c1 = acc[2*h+1]+bc[2*h+1];
            float l0 = acc[8+2*h]+bl[2*h],    l1 = acc[8+2*h+1]+bl[2*h+1];
            float g0 = acc[16+2*h]+bg[2*h],   g1 = acc[16+2*h+1]+bg[2*h+1];
            float pg0 = sigm((c0-c1)/tc), pg1 = 1.f - pg0;
            float q0  = sigm((l0-l1)/tf), q1 = 1.f - q0;
            float r0  = sigm((g0-g1)/tf), r1 = 1.f - r0;
            size_t o = (size_t)row*16 + h*4;
            wgt[o+0] = pg0*q0; wgt[o+1] = pg0*q1; wgt[o+2] = pg1*r0; wgt[o+3] = pg1*r1;
        }
    }
}

// ---------------- mix + per-head RMSNorm ----------------
__global__ void combine_kernel(const float* __restrict__ v, const float* __restrict__ es,
                               const float* __restrict__ el, const float* __restrict__ dl,
                               const float* __restrict__ wgt, const float* __restrict__ onw,
                               float* __restrict__ omix)
{
    const int gw = blockIdx.x*8 + (threadIdx.x>>5);
    const int row = gw >> 2, h = gw & 3;
    const int b = row >> 12, l = row & (Lq-1);
    const int lane = threadIdx.x & 31;
    const size_t gbase = ((size_t)(b*4+h)*Lq + l)*256;
    const float* wp = wgt + (size_t)row*16 + h*4;
    const float w0 = wp[0], w1 = wp[1], w2 = wp[2], w3 = wp[3];

    float4 vals[2];
    float ss = 0.f;
    #pragma unroll
    for (int s=0;s<2;s++){
        const int d = lane*4 + s*128;
        float4 a = *reinterpret_cast<const float4*>(v  + gbase + d);
        float4 b4= *reinterpret_cast<const float4*>(es + gbase + d);
        float4 c4= *reinterpret_cast<const float4*>(dl + gbase + d);
        float4 d4= *reinterpret_cast<const float4*>(el + gbase + d);
        float* av=(float*)&a; float* bv=(float*)&b4; float* cv=(float*)&c4; float* dv=(float*)&d4;
        float* ov=(float*)&vals[s];
        #pragma unroll
        for (int j=0;j<4;j++){
            float val = w0*av[j] + w1*bv[j] + w2*cv[j] + w3*dv[j];
            ov[j] = val;
            ss = fmaf(val, val, ss);
        }
    }
    ss = warp_sum(ss);
    const float rms = rsqrtf(ss*(1.f/256.f) + 1e-5f);
    float* op = omix + (size_t)row*1024 + h*256;
    #pragma unroll
    for (int s=0;s<2;s++){
        const int d = lane*4 + s*128;
        float4 w4 = *reinterpret_cast<const float4*>(onw + d);
        float* wv=(float*)&w4; float* ov=(float*)&vals[s];
        float4 r;
        float* rv=(float*)&r;
        #pragma unroll
        for (int j=0;j<4;j++) rv[j] = tf32r(ov[j]*rms*wv[j]);
        *reinterpret_cast<float4*>(op + d) = r;
    }
}

// ---------------- host ----------------
extern "C" void kernel_launch(void* const* d_in, const int* in_sizes, int n_in,
                              void* d_out, int out_size)
{
    const float* x      = (const float*)d_in[0];
    const float* Wq     = (const float*)d_in[1];
    const float* Wk     = (const float*)d_in[2];
    const float* Wv     = (const float*)d_in[3];
    const float* cqw    = (const float*)d_in[4];
    const float* ckw    = (const float*)d_in[5];
    const float* cvw    = (const float*)d_in[6];
    const float* Wb     = (const float*)d_in[7];
    const float* Wds    = (const float*)d_in[8];
    const float* bds    = (const float*)d_in[9];
    const float* Wdl    = (const float*)d_in[10];
    const float* bdl    = (const float*)d_in[11];
    const float* Wtrunk = (const float*)d_in[12];
    const float* btrunk = (const float*)d_in[13];
    const float* Wcoarse= (const float*)d_in[14];
    const float* bcoarse= (const float*)d_in[15];
    const float* Wlocal = (const float*)d_in[16];
    const float* blocal = (const float*)d_in[17];
    const float* Wglobal= (const float*)d_in[18];
    const float* bglobal= (const float*)d_in[19];
    const float* ltc    = (const float*)d_in[20];
    const float* ltf    = (const float*)d_in[21];
    const float* onw    = (const float*)d_in[22];
    const float* Wo     = (const float*)d_in[23];
    float* out = (float*)d_out;

    float* arena;
    cudaGetSymbolAddress((void**)&arena, g_arena);
    float* qpre = arena + OFF_QPRE;
    float* kpre = arena + OFF_KPRE;
    float* vpre = arena + OFF_VPRE;
    float* qb   = arena + OFF_Q;
    float* kb   = arena + OFF_K;
    float* vb   = arena + OFF_V;
    float* ub   = arena + OFF_UB;
    float* wb   = arena + OFF_WB;
    float* dlt  = arena + OFF_DELTA;
    float* emas = arena + OFF_EMAS;
    float* emal = arena + OFF_EMAL;
    float* omix = arena + OFF_OMIX;
    float* zb   = arena + OFF_Z;
    float* attn = arena + OFF_ATTN;
    float* beta = arena + OFF_BETA;
    float* gs   = arena + OFF_GS;
    float* gl   = arena + OFF_GL;
    float* wgt  = arena + OFF_WGT;
    float* xr   = arena + OFF_XR;
    float* WqR  = arena + OFF_WQR;
    float* WkR  = arena + OFF_WKR;
    float* WvR  = arena + OFF_WVR;
    float* WtR  = arena + OFF_WTR;
    float* WoR  = arena + OFF_WOR;

    cudaFuncSetAttribute(megagemm_kernel,  cudaFuncAttributeMaxDynamicSharedMemorySize, GEMM_SMEM_BYTES);
    cudaFuncSetAttribute(gemm_tf32_kernel, cudaFuncAttributeMaxDynamicSharedMemorySize, GEMM_SMEM_BYTES);
    cudaFuncSetAttribute(chunk_pre_kernel, cudaFuncAttributeMaxDynamicSharedMemorySize, PRE_SMEM_BYTES);
    cudaFuncSetAttribute(scan_ema_kernel,  cudaFuncAttributeMaxDynamicSharedMemorySize, SCAN_SMEM_BYTES);
    cudaFuncSetAttribute(gate_head_kernel, cudaFuncAttributeMaxDynamicSharedMemorySize, GATE_SMEM_BYTES);
    cudaFuncSetAttribute(smallproj_kernel, cudaFuncAttributeMaxDynamicSharedMemorySize, SP_SMEM_BYTES);

    dim3 blk(256);

    // 0: fused rounding of all GEMM inputs
    round_all_kernel<<<20992, blk>>>(x, xr, Wq, WqR, Wk, WkR, Wv, WvR, Wtrunk, WtR, Wo, WoR);

    // 1: beta / decays
    smallproj_kernel<<<MROWS/16, blk, SP_SMEM_BYTES>>>(x, Wb, Wds, bds, Wdl, bdl, beta, gs, gl);

    // 2: fused Q/K/V/trunk projections
    megagemm_kernel<<<dim3(56, MROWS/GBM), blk, GEMM_SMEM_BYTES>>>(
        xr, WqR, WkR, WvR, WtR, btrunk, qpre, kpre, vpre, zb);

    // 3: fused conv+silu + delta precompute  (2 blocks/SM; profiled slot)
    chunk_pre_kernel<<<2048, blk, PRE_SMEM_BYTES>>>(qpre, kpre, vpre, cqw, ckw, cvw,
                                                    qb, kb, vb, beta, ub, wb, attn);

    // 4: fused scan + EMA
    scan_ema_kernel<<<144, blk, SCAN_SMEM_BYTES>>>(qb, kb, ub, wb, attn, dlt,
                                                   vb, gs, gl, emas, emal);

    // 5: gate heads
    gate_head_kernel<<<MROWS/16, blk, GATE_SMEM_BYTES>>>(zb, Wcoarse, bcoarse, Wlocal, blocal,
                                                         Wglobal, bglobal, ltc, ltf, wgt);

    // 6: combine + RMSNorm
    combine_kernel<<<MROWS/2, blk>>>(vb, emas, emal, dlt, wgt, onw, omix);

    // 7: output projection
    gemm_tf32_kernel<<<dim3(1024/GBN, MROWS/GBM), blk, GEMM_SMEM_BYTES>>>(omix, WoR, out, 1024, 1024);
}